// round 7
// baseline (speedup 1.0000x reference)
#include <cuda_runtime.h>
#include <math.h>

#define B     64
#define N     196
#define TT    32
#define STEPS 31
#define VOCAB 32000
#define EMB   256
#define HDIM  512
#define VDIM  256
#define ATTD  256
#define G4    2048

// ---------------- scratch (device globals; no allocation) ----------------
__device__ float g_Uv[B * N * ATTD];     // V @ U_att, precomputed once
__device__ float g_h[B * HDIM];
__device__ float g_c[2][B * HDIM];       // parity double-buffer (lstm fused in proj)
__device__ float g_ctx[B * VDIM];
__device__ float g_hp[2][B * EMB];       // h @ W_proj, double-buffered (cross-stream)
__device__ float g_hW[B * ATTD];         // h @ W_att
__device__ float g_pp[4 * B * 512];      // split-K partials for [hp|hW] GEMM
__device__ float g_gpart[4 * B * G4];    // split-K partials for gates GEMM

__device__ __forceinline__ float sigmoidf_(float x) { return 1.f / (1.f + expf(-x)); }
__device__ __forceinline__ float tanh_fast(float x) {
    float y;
    asm("tanh.approx.f32 %0, %1;" : "=f"(y) : "f"(x));
    return y;
}

// ---------------- packed f32x2 FMA helpers ----------------
typedef unsigned long long ull;
struct Acc44 { ull a[4][2]; };

__device__ __forceinline__ ull fma2(ull a, ull b, ull c) {
    ull d;
    asm("fma.rn.f32x2 %0, %1, %2, %3;" : "=l"(d) : "l"(a), "l"(b), "l"(c));
    return d;
}
__device__ __forceinline__ ull pack2(float x) {
    ull d; unsigned int xi = __float_as_uint(x);
    asm("mov.b64 %0, {%1, %1};" : "=l"(d) : "r"(xi));
    return d;
}
__device__ __forceinline__ void acc_zero(Acc44& A) {
    #pragma unroll
    for (int i = 0; i < 4; i++) { A.a[i][0] = 0ull; A.a[i][1] = 0ull; }
}
__device__ __forceinline__ void mma44(Acc44& A, float4 xf, ulonglong2 wf) {
    ull h;
    h = pack2(xf.x); A.a[0][0] = fma2(h, wf.x, A.a[0][0]); A.a[0][1] = fma2(h, wf.y, A.a[0][1]);
    h = pack2(xf.y); A.a[1][0] = fma2(h, wf.x, A.a[1][0]); A.a[1][1] = fma2(h, wf.y, A.a[1][1]);
    h = pack2(xf.z); A.a[2][0] = fma2(h, wf.x, A.a[2][0]); A.a[2][1] = fma2(h, wf.y, A.a[2][1]);
    h = pack2(xf.w); A.a[3][0] = fma2(h, wf.x, A.a[3][0]); A.a[3][1] = fma2(h, wf.y, A.a[3][1]);
}
__device__ __forceinline__ float4 unpack44(const Acc44& A, int i) {
    unsigned int l0, h0, l1, h1;
    asm("mov.b64 {%0,%1}, %2;" : "=r"(l0), "=r"(h0) : "l"(A.a[i][0]));
    asm("mov.b64 {%0,%1}, %2;" : "=r"(l1), "=r"(h1) : "l"(A.a[i][1]));
    return make_float4(__uint_as_float(l0), __uint_as_float(h0),
                       __uint_as_float(l1), __uint_as_float(h1));
}

// ---------------- init: feat_mean -> h0, c0 ----------------
// grid = B, block = 512
__global__ void k_init_hc(const float* __restrict__ V,
                          const float* __restrict__ Wh, const float* __restrict__ bh,
                          const float* __restrict__ Wc, const float* __restrict__ bc) {
    int b = blockIdx.x, tid = threadIdx.x;
    __shared__ float fm[VDIM];
    if (tid < VDIM) {
        const float* vp = V + (size_t)b * N * VDIM + tid;
        float s = 0.f;
        for (int n = 0; n < N; n++) s += vp[(size_t)n * VDIM];
        fm[tid] = s * (1.f / (float)N);
    }
    __syncthreads();
    int j = tid;
    float ah = bh[j], ac = bc[j];
    #pragma unroll 4
    for (int v = 0; v < VDIM; v++) {
        float f = fm[v];
        ah += f * Wh[(size_t)v * HDIM + j];
        ac += f * Wc[(size_t)v * HDIM + j];
    }
    g_h[b * HDIM + j] = tanhf(ah);
    g_c[0][b * HDIM + j] = tanhf(ac);
}

// ---------------- Uv = V @ U_att (once) ----------------
// grid = B*N/16 = 784, block = 256
#define UV_ROWS 16
__global__ void k_uv(const float* __restrict__ V, const float* __restrict__ U) {
    __shared__ float Vs[UV_ROWS * VDIM];
    int r0 = blockIdx.x * UV_ROWS;
    int tid = threadIdx.x;
    for (int i = tid; i < UV_ROWS * VDIM; i += 256)
        Vs[i] = V[(size_t)r0 * VDIM + i];
    __syncthreads();
    float acc[UV_ROWS];
    #pragma unroll
    for (int i = 0; i < UV_ROWS; i++) acc[i] = 0.f;
    int a = tid;
    #pragma unroll 4
    for (int v = 0; v < VDIM; v++) {
        float u = U[(size_t)v * ATTD + a];
        #pragma unroll
        for (int i = 0; i < UV_ROWS; i++) acc[i] += Vs[i * VDIM + v] * u;
    }
    #pragma unroll
    for (int i = 0; i < UV_ROWS; i++)
        g_Uv[(size_t)(r0 + i) * ATTD + a] = acc[i];
}

// ---------------- fused attention: energies + softmax + ctx ----------------
// grid = B, block = 256
__global__ void k_att(const float* __restrict__ vatt, const float* __restrict__ V) {
    int b = blockIdx.x, tid = threadIdx.x;
    __shared__ float hWs[ATTD];
    __shared__ float vs[ATTD];
    __shared__ float es[256];
    __shared__ float red[256];
    hWs[tid] = g_hW[b * ATTD + tid];
    vs[tid] = vatt[tid];
    __syncthreads();
    int warp = tid >> 5, lane = tid & 31;
    for (int n = warp; n < N; n += 8) {
        const float* uv = g_Uv + (size_t)(b * N + n) * ATTD;
        float p = 0.f;
        #pragma unroll
        for (int j = 0; j < 8; j++) {
            int a = lane + 32 * j;
            p += tanh_fast(hWs[a] + uv[a]) * vs[a];
        }
        #pragma unroll
        for (int off = 16; off > 0; off >>= 1)
            p += __shfl_down_sync(0xffffffffu, p, off);
        if (lane == 0) es[n] = p;
    }
    __syncthreads();
    float v = (tid < N) ? es[tid] : -INFINITY;
    red[tid] = v;
    __syncthreads();
    for (int s = 128; s > 0; s >>= 1) {
        if (tid < s) red[tid] = fmaxf(red[tid], red[tid + s]);
        __syncthreads();
    }
    float mx = red[0];
    __syncthreads();
    float ex = (tid < N) ? expf(v - mx) : 0.f;
    red[tid] = ex;
    __syncthreads();
    for (int s = 128; s > 0; s >>= 1) {
        if (tid < s) red[tid] += red[tid + s];
        __syncthreads();
    }
    float inv = 1.f / red[0];
    __syncthreads();
    if (tid < N) es[tid] = ex * inv;
    __syncthreads();
    // ctx: each thread one v-dim
    const float* vp = V + (size_t)b * N * VDIM + tid;
    float acc = 0.f;
    #pragma unroll 4
    for (int n = 0; n < N; n++) acc += es[n] * vp[(size_t)n * VDIM];
    g_ctx[b * VDIM + tid] = acc;
}

// ---------------- gates GEMM: [64,1024] @ [1024,2048], split-K ----------------
// grid = dim3(32, 4), block = 256, dyn smem = 135168
__global__ void k_gates(const float* __restrict__ embed, const int* __restrict__ y,
                        const float* __restrict__ Wih, const float* __restrict__ Whh, int t) {
    extern __shared__ float sm[];
    float* Xs = sm;               // [256 kk][68 pad] X^T tile (bb fastest)
    float* Ws = sm + 256 * 68;    // [256 kk][64 jj]
    int j0 = blockIdx.x * 64;
    int kc = blockIdx.y;
    int tid = threadIdx.x;

    for (int idx = tid; idx < B * 256; idx += 256) {
        int kk = idx & 255, bb = idx >> 8;
        float x;
        if (kc == 0)      x = embed[(size_t)y[bb * TT + t] * EMB + kk];
        else if (kc == 1) x = g_ctx[bb * VDIM + kk];
        else if (kc == 2) x = g_h[bb * HDIM + kk];
        else              x = g_h[bb * HDIM + 256 + kk];
        Xs[kk * 68 + bb] = x;
    }
    const float* W = (kc < 2) ? (Wih + (size_t)(kc * 256) * G4)
                              : (Whh + (size_t)((kc - 2) * 256) * G4);
    for (int idx = tid; idx < 256 * 64; idx += 256) {
        int kk = idx >> 6, jj = idx & 63;
        Ws[idx] = W[(size_t)kk * G4 + j0 + jj];
    }
    __syncthreads();

    int tx = tid & 15, ty = tid >> 4;
    Acc44 A; acc_zero(A);
    #pragma unroll 4
    for (int kk = 0; kk < 256; kk++) {
        float4 xf = *(const float4*)&Xs[kk * 68 + ty * 4];
        ulonglong2 wf = *(const ulonglong2*)&Ws[kk * 64 + tx * 4];
        mma44(A, xf, wf);
    }
    float* gp = g_gpart + (size_t)kc * B * G4;
    #pragma unroll
    for (int i = 0; i < 4; i++) {
        int bb = ty * 4 + i;
        *(float4*)&gp[(size_t)bb * G4 + j0 + tx * 4] = unpack44(A, i);
    }
}

// ---------------- proj GEMM with fused LSTM update ----------------
// [hp|hW] = h_new[64,512] @ [Wproj|Watt][512,512], split-K
// grid = dim3(8 jtiles, 4 kchunks), block = 256, dyn smem = 67584
// do_lstm: compute h_new from gate partials (jtile 0 also commits g_h, g_c)
__global__ void k_proj(const float* __restrict__ Wproj, const float* __restrict__ Watt,
                       const float* __restrict__ bih, const float* __restrict__ bhh,
                       int parity, int do_lstm) {
    extern __shared__ float sm[];
    float* Xs = sm;               // [128 kk][68 pad] h^T chunk (bb fastest)
    float* Ws = sm + 128 * 68;    // [128 kk][64 jj]
    int j0 = blockIdx.x * 64;
    int kc = blockIdx.y;
    int tid = threadIdx.x;

    if (do_lstm) {
        for (int idx = tid; idx < B * 128; idx += 256) {
            int kk = idx & 127, bb = idx >> 7;
            int j = kc * 128 + kk;
            float gi = bih[j]        + bhh[j];
            float gf = bih[512 + j]  + bhh[512 + j];
            float gg = bih[1024 + j] + bhh[1024 + j];
            float go = bih[1536 + j] + bhh[1536 + j];
            #pragma unroll
            for (int p = 0; p < 4; p++) {
                const float* gp = g_gpart + (size_t)p * B * G4 + (size_t)bb * G4;
                gi += gp[j]; gf += gp[512 + j]; gg += gp[1024 + j]; go += gp[1536 + j];
            }
            float c = sigmoidf_(gf) * g_c[parity][bb * HDIM + j] + sigmoidf_(gi) * tanhf(gg);
            float h = sigmoidf_(go) * tanhf(c);
            if (blockIdx.x == 0) {
                g_c[parity ^ 1][bb * HDIM + j] = c;
                g_h[bb * HDIM + j] = h;
            }
            Xs[kk * 68 + bb] = h;
        }
    } else {
        for (int idx = tid; idx < B * 128; idx += 256) {
            int kk = idx & 127, bb = idx >> 7;
            Xs[kk * 68 + bb] = g_h[bb * HDIM + kc * 128 + kk];
        }
    }
    const float* W = (j0 < 256) ? (Wproj + j0) : (Watt + (j0 - 256));
    for (int idx = tid; idx < 128 * 64; idx += 256) {
        int kk = idx >> 6, jj = idx & 63;
        Ws[idx] = W[(size_t)(kc * 128 + kk) * 256 + jj];
    }
    __syncthreads();

    int tx = tid & 15, ty = tid >> 4;
    Acc44 A; acc_zero(A);
    #pragma unroll 4
    for (int kk = 0; kk < 128; kk++) {
        float4 xf = *(const float4*)&Xs[kk * 68 + ty * 4];
        ulonglong2 wf = *(const ulonglong2*)&Ws[kk * 64 + tx * 4];
        mma44(A, xf, wf);
    }
    float* pp = g_pp + (size_t)kc * B * 512;
    #pragma unroll
    for (int i = 0; i < 4; i++) {
        int bb = ty * 4 + i;
        *(float4*)&pp[(size_t)bb * 512 + j0 + tx * 4] = unpack44(A, i);
    }
}

// ---------------- reduce split-K partials -> g_hp[buf], g_hW ----------------
// grid = B, block = 512
__global__ void k_hphw(int buf) {
    int b = blockIdx.x, j = threadIdx.x;
    size_t o = (size_t)b * 512 + j;
    float s = g_pp[o] + g_pp[B * 512 + o] + g_pp[2 * B * 512 + o] + g_pp[3 * B * 512 + o];
    if (j < 256) g_hp[buf][b * EMB + j] = s;
    else         g_hW[b * ATTD + (j - 256)] = s;
}

// ---------------- logits = hp @ embed^T (K chunked, f32x2) ----------------
// grid = VOCAB/64 = 500, block = 256, dyn smem = 69632
__global__ void k_logits(const float* __restrict__ embed, float* __restrict__ out,
                         int t, int buf) {
    extern __shared__ float sm[];
    float* Hs = sm;               // [128 kk][68 pad] : hp^T chunk (bb fastest)
    float* Es = sm + 128 * 68;    // [128 kk][68 pad] : embed^T chunk (vv fastest)
    int v0 = blockIdx.x * 64;
    int tid = threadIdx.x;
    int tx = tid & 15, ty = tid >> 4;
    const float* hp = g_hp[buf];

    Acc44 A; acc_zero(A);
    #pragma unroll
    for (int kc2 = 0; kc2 < 2; kc2++) {
        int kb = kc2 * 128;
        for (int idx = tid; idx < B * 128; idx += 256) {
            int kk = idx & 127, bb = idx >> 7;
            Hs[kk * 68 + bb] = hp[bb * EMB + kb + kk];
        }
        for (int idx = tid; idx < 64 * 128; idx += 256) {
            int kk = idx & 127, vv = idx >> 7;
            Es[kk * 68 + vv] = embed[(size_t)(v0 + vv) * EMB + kb + kk];
        }
        __syncthreads();
        #pragma unroll 4
        for (int kk = 0; kk < 128; kk++) {
            float4 hf = *(const float4*)&Hs[kk * 68 + ty * 4];
            ulonglong2 ef = *(const ulonglong2*)&Es[kk * 68 + tx * 4];
            mma44(A, hf, ef);
        }
        __syncthreads();
    }
    #pragma unroll
    for (int i = 0; i < 4; i++) {
        int bb = ty * 4 + i;
        float* op = out + ((size_t)bb * STEPS + t) * VOCAB + v0 + tx * 4;
        *(float4*)op = unpack44(A, i);
    }
}

// ---------------- launch ----------------
extern "C" void kernel_launch(void* const* d_in, const int* in_sizes, int n_in,
                              void* d_out, int out_size) {
    const float* V      = (const float*)d_in[0];
    const int*   y      = (const int*)  d_in[1];
    const float* embed  = (const float*)d_in[2];
    const float* W_att  = (const float*)d_in[3];
    const float* U_att  = (const float*)d_in[4];
    const float* v_att  = (const float*)d_in[5];
    const float* W_ih   = (const float*)d_in[6];
    const float* W_hh   = (const float*)d_in[7];
    const float* b_ih   = (const float*)d_in[8];
    const float* b_hh   = (const float*)d_in[9];
    const float* W_inith = (const float*)d_in[10];
    const float* b_inith = (const float*)d_in[11];
    const float* W_initc = (const float*)d_in[12];
    const float* b_initc = (const float*)d_in[13];
    const float* W_proj  = (const float*)d_in[14];
    float* out = (float*)d_out;

    const int SMEM_GATES  = (256 * 68 + 256 * 64) * sizeof(float);  // 135168
    const int SMEM_PROJ   = (128 * 68 + 128 * 64) * sizeof(float);  // 67584
    const int SMEM_LOGITS = (2 * 128 * 68) * sizeof(float);         // 69632
    cudaFuncSetAttribute(k_gates,  cudaFuncAttributeMaxDynamicSharedMemorySize, SMEM_GATES);
    cudaFuncSetAttribute(k_proj,   cudaFuncAttributeMaxDynamicSharedMemorySize, SMEM_PROJ);
    cudaFuncSetAttribute(k_logits, cudaFuncAttributeMaxDynamicSharedMemorySize, SMEM_LOGITS);

    // second stream + events for logits overlap (created fresh each call;
    // intentionally leaked — kernel_launch is called only a handful of times)
    cudaStream_t s2;
    cudaStreamCreateWithFlags(&s2, cudaStreamNonBlocking);
    cudaEvent_t eA, eB0, eB1;
    cudaEventCreateWithFlags(&eA,  cudaEventDisableTiming);
    cudaEventCreateWithFlags(&eB0, cudaEventDisableTiming);
    cudaEventCreateWithFlags(&eB1, cudaEventDisableTiming);

    k_init_hc<<<B, 512>>>(V, W_inith, b_inith, W_initc, b_initc);
    k_uv<<<(B * N) / UV_ROWS, 256>>>(V, U_att);
    // hW(h0) for step 0 (writes hp into unused buf 1)
    k_proj<<<dim3(8, 4), 256, SMEM_PROJ>>>(W_proj, W_att, b_ih, b_hh, 0, 0);
    k_hphw<<<B, 512>>>(1);

    for (int t = 0; t < STEPS; t++) {
        k_att<<<B, 256>>>(v_att, V);
        k_gates<<<dim3(32, 4), 256, SMEM_GATES>>>(embed, y, W_ih, W_hh, t);
        // hp buffer (t&1) is about to be overwritten by hphw(t):
        // ensure logits(t-2), which read it, has finished.
        if (t >= 2) cudaStreamWaitEvent(0, (t & 1) ? eB1 : eB0, 0);
        k_proj<<<dim3(8, 4), 256, SMEM_PROJ>>>(W_proj, W_att, b_ih, b_hh, t & 1, 1);
        k_hphw<<<B, 512>>>(t & 1);
        cudaEventRecord(eA, 0);
        cudaStreamWaitEvent(s2, eA, 0);
        k_logits<<<VOCAB / 64, 256, SMEM_LOGITS, s2>>>(embed, out, t, t & 1);
        cudaEventRecord((t & 1) ? eB1 : eB0, s2);
    }
    // join logits stream back into the capture origin
    cudaStreamWaitEvent(0, eB0, 0);
    cudaStreamWaitEvent(0, eB1, 0);
}

// round 9
// speedup vs baseline: 1.0214x; 1.0214x over previous
#include <cuda_runtime.h>
#include <cuda_bf16.h>
#include <math.h>

#define B     64
#define N     196
#define TT    32
#define STEPS 31
#define VOCAB 32000
#define EMB   256
#define HDIM  512
#define VDIM  256
#define ATTD  256
#define G4    2048

// ---------------- scratch (device globals; no allocation) ----------------
__device__ float g_Uv[B * N * ATTD];
__device__ float g_h[B * HDIM];
__device__ float g_c[2][B * HDIM];        // parity double-buffer
__device__ float g_ctx[B * VDIM];
__device__ float g_hW[B * ATTD];
__device__ float g_pp[4 * B * 512];       // split-K partials for [hp|hW]
__device__ float g_gpart[4 * B * G4];     // split-K partials for gates
__device__ __align__(16) __nv_bfloat16 g_hpb[128 * EMB];        // rows 0-63 hi, 64-127 lo
__device__ __align__(16) __nv_bfloat16 g_eh[(size_t)VOCAB * EMB];
__device__ __align__(16) __nv_bfloat16 g_el[(size_t)VOCAB * EMB];

__device__ __forceinline__ float sigmoidf_(float x) { return 1.f / (1.f + expf(-x)); }
__device__ __forceinline__ float tanh_fast(float x) {
    float y;
    asm("tanh.approx.f32 %0, %1;" : "=f"(y) : "f"(x));
    return y;
}

// ---------------- packed f32x2 FMA helpers (SIMT GEMMs) ----------------
typedef unsigned long long ull;
struct Acc44 { ull a[4][2]; };
__device__ __forceinline__ ull fma2(ull a, ull b, ull c) {
    ull d; asm("fma.rn.f32x2 %0, %1, %2, %3;" : "=l"(d) : "l"(a), "l"(b), "l"(c));
    return d;
}
__device__ __forceinline__ ull pack2(float x) {
    ull d; unsigned int xi = __float_as_uint(x);
    asm("mov.b64 %0, {%1, %1};" : "=l"(d) : "r"(xi));
    return d;
}
__device__ __forceinline__ void acc_zero(Acc44& A) {
    #pragma unroll
    for (int i = 0; i < 4; i++) { A.a[i][0] = 0ull; A.a[i][1] = 0ull; }
}
__device__ __forceinline__ void mma44(Acc44& A, float4 xf, ulonglong2 wf) {
    ull h;
    h = pack2(xf.x); A.a[0][0] = fma2(h, wf.x, A.a[0][0]); A.a[0][1] = fma2(h, wf.y, A.a[0][1]);
    h = pack2(xf.y); A.a[1][0] = fma2(h, wf.x, A.a[1][0]); A.a[1][1] = fma2(h, wf.y, A.a[1][1]);
    h = pack2(xf.z); A.a[2][0] = fma2(h, wf.x, A.a[2][0]); A.a[2][1] = fma2(h, wf.y, A.a[2][1]);
    h = pack2(xf.w); A.a[3][0] = fma2(h, wf.x, A.a[3][0]); A.a[3][1] = fma2(h, wf.y, A.a[3][1]);
}
__device__ __forceinline__ float4 unpack44(const Acc44& A, int i) {
    unsigned int l0, h0, l1, h1;
    asm("mov.b64 {%0,%1}, %2;" : "=r"(l0), "=r"(h0) : "l"(A.a[i][0]));
    asm("mov.b64 {%0,%1}, %2;" : "=r"(l1), "=r"(h1) : "l"(A.a[i][1]));
    return make_float4(__uint_as_float(l0), __uint_as_float(h0),
                       __uint_as_float(l1), __uint_as_float(h1));
}

__device__ __forceinline__ unsigned smem_u32(const void* p) {
    unsigned a;
    asm("{ .reg .u64 t; cvta.to.shared.u64 t, %1; cvt.u32.u64 %0, t; }" : "=r"(a) : "l"(p));
    return a;
}

// ---------------- init: feat_mean -> h0, c0 ----------------
__global__ void k_init_hc(const float* __restrict__ V,
                          const float* __restrict__ Wh, const float* __restrict__ bh,
                          const float* __restrict__ Wc, const float* __restrict__ bc) {
    int b = blockIdx.x, tid = threadIdx.x;
    __shared__ float fm[VDIM];
    if (tid < VDIM) {
        const float* vp = V + (size_t)b * N * VDIM + tid;
        float s = 0.f;
        for (int n = 0; n < N; n++) s += vp[(size_t)n * VDIM];
        fm[tid] = s * (1.f / (float)N);
    }
    __syncthreads();
    int j = tid;
    float ah = bh[j], ac = bc[j];
    #pragma unroll 4
    for (int v = 0; v < VDIM; v++) {
        float f = fm[v];
        ah += f * Wh[(size_t)v * HDIM + j];
        ac += f * Wc[(size_t)v * HDIM + j];
    }
    g_h[b * HDIM + j] = tanhf(ah);
    g_c[0][b * HDIM + j] = tanhf(ac);
}

// ---------------- Uv = V @ U_att (once) ----------------
#define UV_ROWS 16
__global__ void k_uv(const float* __restrict__ V, const float* __restrict__ U) {
    __shared__ float Vs[UV_ROWS * VDIM];
    int r0 = blockIdx.x * UV_ROWS;
    int tid = threadIdx.x;
    for (int i = tid; i < UV_ROWS * VDIM; i += 256)
        Vs[i] = V[(size_t)r0 * VDIM + i];
    __syncthreads();
    float acc[UV_ROWS];
    #pragma unroll
    for (int i = 0; i < UV_ROWS; i++) acc[i] = 0.f;
    int a = tid;
    #pragma unroll 4
    for (int v = 0; v < VDIM; v++) {
        float u = U[(size_t)v * ATTD + a];
        #pragma unroll
        for (int i = 0; i < UV_ROWS; i++) acc[i] += Vs[i * VDIM + v] * u;
    }
    #pragma unroll
    for (int i = 0; i < UV_ROWS; i++)
        g_Uv[(size_t)(r0 + i) * ATTD + a] = acc[i];
}

// ---------------- embed -> bf16 hi/lo (once) ----------------
__global__ void k_esplit(const float* __restrict__ e) {
    size_t i = ((size_t)blockIdx.x * 256 + threadIdx.x) * 2;
    float2 v = *(const float2*)(e + i);
    __nv_bfloat16 h0 = __float2bfloat16(v.x);
    __nv_bfloat16 h1 = __float2bfloat16(v.y);
    __nv_bfloat16 l0 = __float2bfloat16(v.x - __bfloat162float(h0));
    __nv_bfloat16 l1 = __float2bfloat16(v.y - __bfloat162float(h1));
    *(__nv_bfloat162*)(g_eh + i) = __nv_bfloat162(h0, h1);
    *(__nv_bfloat162*)(g_el + i) = __nv_bfloat162(l0, l1);
}

// ---------------- fused attention: energies + softmax + ctx ----------------
__global__ void k_att(const float* __restrict__ vatt, const float* __restrict__ V) {
    int b = blockIdx.x, tid = threadIdx.x;
    __shared__ float hWs[ATTD];
    __shared__ float vs[ATTD];
    __shared__ float es[256];
    __shared__ float red[256];
    hWs[tid] = g_hW[b * ATTD + tid];
    vs[tid] = vatt[tid];
    __syncthreads();
    int warp = tid >> 5, lane = tid & 31;
    for (int n = warp; n < N; n += 8) {
        const float* uv = g_Uv + (size_t)(b * N + n) * ATTD;
        float p = 0.f;
        #pragma unroll
        for (int j = 0; j < 8; j++) {
            int a = lane + 32 * j;
            p += tanh_fast(hWs[a] + uv[a]) * vs[a];
        }
        #pragma unroll
        for (int off = 16; off > 0; off >>= 1)
            p += __shfl_down_sync(0xffffffffu, p, off);
        if (lane == 0) es[n] = p;
    }
    __syncthreads();
    float v = (tid < N) ? es[tid] : -INFINITY;
    red[tid] = v;
    __syncthreads();
    for (int s = 128; s > 0; s >>= 1) {
        if (tid < s) red[tid] = fmaxf(red[tid], red[tid + s]);
        __syncthreads();
    }
    float mx = red[0];
    __syncthreads();
    float ex = (tid < N) ? expf(v - mx) : 0.f;
    red[tid] = ex;
    __syncthreads();
    for (int s = 128; s > 0; s >>= 1) {
        if (tid < s) red[tid] += red[tid + s];
        __syncthreads();
    }
    float inv = 1.f / red[0];
    __syncthreads();
    if (tid < N) es[tid] = ex * inv;
    __syncthreads();
    const float* vp = V + (size_t)b * N * VDIM + tid;
    float acc = 0.f;
    #pragma unroll 4
    for (int n = 0; n < N; n++) acc += es[n] * vp[(size_t)n * VDIM];
    g_ctx[b * VDIM + tid] = acc;
}

// ---------------- gates GEMM: [64,1024] @ [1024,2048], split-K ----------------
__global__ void k_gates(const float* __restrict__ embed, const int* __restrict__ y,
                        const float* __restrict__ Wih, const float* __restrict__ Whh, int t) {
    extern __shared__ float sm[];
    float* Xs = sm;
    float* Ws = sm + 256 * 68;
    int j0 = blockIdx.x * 64;
    int kc = blockIdx.y;
    int tid = threadIdx.x;

    for (int idx = tid; idx < B * 256; idx += 256) {
        int kk = idx & 255, bb = idx >> 8;
        float x;
        if (kc == 0)      x = embed[(size_t)y[bb * TT + t] * EMB + kk];
        else if (kc == 1) x = g_ctx[bb * VDIM + kk];
        else if (kc == 2) x = g_h[bb * HDIM + kk];
        else              x = g_h[bb * HDIM + 256 + kk];
        Xs[kk * 68 + bb] = x;
    }
    const float* W = (kc < 2) ? (Wih + (size_t)(kc * 256) * G4)
                              : (Whh + (size_t)((kc - 2) * 256) * G4);
    for (int idx = tid; idx < 256 * 64; idx += 256) {
        int kk = idx >> 6, jj = idx & 63;
        Ws[idx] = W[(size_t)kk * G4 + j0 + jj];
    }
    __syncthreads();

    int tx = tid & 15, ty = tid >> 4;
    Acc44 A; acc_zero(A);
    #pragma unroll 4
    for (int kk = 0; kk < 256; kk++) {
        float4 xf = *(const float4*)&Xs[kk * 68 + ty * 4];
        ulonglong2 wf = *(const ulonglong2*)&Ws[kk * 64 + tx * 4];
        mma44(A, xf, wf);
    }
    float* gp = g_gpart + (size_t)kc * B * G4;
    #pragma unroll
    for (int i = 0; i < 4; i++) {
        int bb = ty * 4 + i;
        *(float4*)&gp[(size_t)bb * G4 + j0 + tx * 4] = unpack44(A, i);
    }
}

// ---------------- proj GEMM with fused LSTM update ----------------
__global__ void k_proj(const float* __restrict__ Wproj, const float* __restrict__ Watt,
                       const float* __restrict__ bih, const float* __restrict__ bhh,
                       int parity, int do_lstm) {
    extern __shared__ float sm[];
    float* Xs = sm;
    float* Ws = sm + 128 * 68;
    int j0 = blockIdx.x * 64;
    int kc = blockIdx.y;
    int tid = threadIdx.x;

    if (do_lstm) {
        for (int idx = tid; idx < B * 128; idx += 256) {
            int kk = idx & 127, bb = idx >> 7;
            int j = kc * 128 + kk;
            float gi = bih[j]        + bhh[j];
            float gf = bih[512 + j]  + bhh[512 + j];
            float gg = bih[1024 + j] + bhh[1024 + j];
            float go = bih[1536 + j] + bhh[1536 + j];
            #pragma unroll
            for (int p = 0; p < 4; p++) {
                const float* gp = g_gpart + (size_t)p * B * G4 + (size_t)bb * G4;
                gi += gp[j]; gf += gp[512 + j]; gg += gp[1024 + j]; go += gp[1536 + j];
            }
            float c = sigmoidf_(gf) * g_c[parity][bb * HDIM + j] + sigmoidf_(gi) * tanhf(gg);
            float h = sigmoidf_(go) * tanhf(c);
            if (blockIdx.x == 0) {
                g_c[parity ^ 1][bb * HDIM + j] = c;
                g_h[bb * HDIM + j] = h;
            }
            Xs[kk * 68 + bb] = h;
        }
    } else {
        for (int idx = tid; idx < B * 128; idx += 256) {
            int kk = idx & 127, bb = idx >> 7;
            Xs[kk * 68 + bb] = g_h[bb * HDIM + kc * 128 + kk];
        }
    }
    const float* W = (j0 < 256) ? (Wproj + j0) : (Watt + (j0 - 256));
    for (int idx = tid; idx < 128 * 64; idx += 256) {
        int kk = idx >> 6, jj = idx & 63;
        Ws[idx] = W[(size_t)(kc * 128 + kk) * 256 + jj];
    }
    __syncthreads();

    int tx = tid & 15, ty = tid >> 4;
    Acc44 A; acc_zero(A);
    #pragma unroll 4
    for (int kk = 0; kk < 128; kk++) {
        float4 xf = *(const float4*)&Xs[kk * 68 + ty * 4];
        ulonglong2 wf = *(const ulonglong2*)&Ws[kk * 64 + tx * 4];
        mma44(A, xf, wf);
    }
    float* pp = g_pp + (size_t)kc * B * 512;
    #pragma unroll
    for (int i = 0; i < 4; i++) {
        int bb = ty * 4 + i;
        *(float4*)&pp[(size_t)bb * 512 + j0 + tx * 4] = unpack44(A, i);
    }
}

// ---------------- reduce partials -> g_hpb (bf16 hi/lo) + g_hW ----------------
__global__ void k_split() {
    int b = blockIdx.x, j = threadIdx.x;
    size_t o = (size_t)b * 512 + j;
    float s = g_pp[o] + g_pp[B * 512 + o] + g_pp[2 * B * 512 + o] + g_pp[3 * B * 512 + o];
    if (j < 256) {
        __nv_bfloat16 hi = __float2bfloat16(s);
        __nv_bfloat16 lo = __float2bfloat16(s - __bfloat162float(hi));
        g_hpb[b * EMB + j] = hi;
        g_hpb[(64 + b) * EMB + j] = lo;
    } else {
        g_hW[b * ATTD + (j - 256)] = s;
    }
}

// ---------------- logits via mma.sync bf16 hi/lo split ----------------
// grid = 250, block = 256 (8 warps, 4 m-rows x 2 n-cols), dyn smem = 102400
// A = [128 m][256 k] bf16 (m 0-63 hi(hp), 64-127 lo(hp)); B = embed hi & lo tiles.
// D[m][n] over K accumulates A@Bh + A@Bl; logits[b][v] = D[b] + D[b+64].
#define SA  0
#define SBH 32768
#define SBL (SBH + 34816)
#define SM_LOG (SBL + 34816)   // 102400

__global__ void __launch_bounds__(256, 2) k_logits_mma(float* __restrict__ out, int t) {
    extern __shared__ char smc[];
    const unsigned sb = smem_u32(smc);
    int tid = threadIdx.x;
    int wid = tid >> 5, lane = tid & 31;
    int wr = wid & 3, wc = wid >> 2;        // warp tile: rows wr*32.., cols wc*64..
    int v0 = blockIdx.x * 128;

    float d[16][4];                          // frag f = mi*8+nf
    #pragma unroll
    for (int f = 0; f < 16; f++) { d[f][0] = d[f][1] = d[f][2] = d[f][3] = 0.f; }

    #pragma unroll
    for (int kc = 0; kc < 2; kc++) {
        // A chunk: g_hpb[m][kc*128..+127] -> swizzled smem
        for (int i = tid; i < 2048; i += 256) {
            int m = i >> 4, u = i & 15;
            *(uint4*)(smc + SA + m * 256 + ((u ^ (m & 7)) << 4)) =
                *(const uint4*)((const char*)g_hpb + (size_t)m * 512 + kc * 256 + u * 16);
        }
        // B chunks (hi & lo), rows padded to 272B
        for (int i = tid; i < 2048; i += 256) {
            int n = i >> 4, u = i & 15;
            size_t go = (size_t)(v0 + n) * 512 + kc * 256 + u * 16;
            *(uint4*)(smc + SBH + n * 272 + u * 16) = *(const uint4*)((const char*)g_eh + go);
            *(uint4*)(smc + SBL + n * 272 + u * 16) = *(const uint4*)((const char*)g_el + go);
        }
        __syncthreads();

        #pragma unroll
        for (int ks = 0; ks < 8; ks++) {
            // A fragments (2 per warp) via ldmatrix.x4
            unsigned a[2][4];
            #pragma unroll
            for (int mi = 0; mi < 2; mi++) {
                int m = wr * 32 + mi * 16 + ((lane >> 3) & 1) * 8 + (lane & 7);
                int u = ks * 2 + (lane >> 4);
                unsigned addr = sb + SA + m * 256 + ((u ^ (m & 7)) << 4);
                asm volatile(
                    "ldmatrix.sync.aligned.m8n8.x4.shared.b16 {%0,%1,%2,%3}, [%4];"
                    : "=r"(a[mi][0]), "=r"(a[mi][1]), "=r"(a[mi][2]), "=r"(a[mi][3])
                    : "r"(addr));
            }
            // B fragments: thread holds B[n0+lane/4][k + (lane%4)*2 (+8)]
            int brow = lane >> 2;
            int bk = ks * 16 + (lane & 3) * 2;
            #pragma unroll
            for (int nf = 0; nf < 8; nf++) {
                int n = wc * 64 + nf * 8 + brow;
                unsigned bo = n * 272 + bk * 2;
                unsigned bh0 = *(const unsigned*)(smc + SBH + bo);
                unsigned bh1 = *(const unsigned*)(smc + SBH + bo + 16);
                unsigned bl0 = *(const unsigned*)(smc + SBL + bo);
                unsigned bl1 = *(const unsigned*)(smc + SBL + bo + 16);
                #pragma unroll
                for (int mi = 0; mi < 2; mi++) {
                    int f = mi * 8 + nf;
                    asm volatile(
                        "mma.sync.aligned.m16n8k16.row.col.f32.bf16.bf16.f32 "
                        "{%0,%1,%2,%3}, {%4,%5,%6,%7}, {%8,%9}, {%0,%1,%2,%3};"
                        : "+f"(d[f][0]), "+f"(d[f][1]), "+f"(d[f][2]), "+f"(d[f][3])
                        : "r"(a[mi][0]), "r"(a[mi][1]), "r"(a[mi][2]), "r"(a[mi][3]),
                          "r"(bh0), "r"(bh1));
                    asm volatile(
                        "mma.sync.aligned.m16n8k16.row.col.f32.bf16.bf16.f32 "
                        "{%0,%1,%2,%3}, {%4,%5,%6,%7}, {%8,%9}, {%0,%1,%2,%3};"
                        : "+f"(d[f][0]), "+f"(d[f][1]), "+f"(d[f][2]), "+f"(d[f][3])
                        : "r"(a[mi][0]), "r"(a[mi][1]), "r"(a[mi][2]), "r"(a[mi][3]),
                          "r"(bl0), "r"(bl1));
                }
            }
        }
        __syncthreads();
    }

    // epilogue: lo rows (m>=64) -> smem (reuse A region), hi rows add + store
    float* epi = (float*)(smc + SA);        // [64 m][128 n]
    if (wr >= 2) {
        #pragma unroll
        for (int mi = 0; mi < 2; mi++) {
            int r0 = (wr - 2) * 32 + mi * 16 + (lane >> 2);
            #pragma unroll
            for (int nf = 0; nf < 8; nf++) {
                int f = mi * 8 + nf;
                int col = wc * 64 + nf * 8 + (lane & 3) * 2;
                epi[r0 * 128 + col]           = d[f][0];
                epi[r0 * 128 + col + 1]       = d[f][1];
                epi[(r0 + 8) * 128 + col]     = d[f][2];
                epi[(r0 + 8) * 128 + col + 1] = d[f][3];
            }
        }
    }
    __syncthreads();
    if (wr < 2) {
        #pragma unroll
        for (int mi = 0; mi < 2; mi++) {
            int b0 = wr * 32 + mi * 16 + (lane >> 2);
            #pragma unroll
            for (int nf = 0; nf < 8; nf++) {
                int f = mi * 8 + nf;
                int col = wc * 64 + nf * 8 + (lane & 3) * 2;
                float2 r0v = make_float2(d[f][0] + epi[b0 * 128 + col],
                                         d[f][1] + epi[b0 * 128 + col + 1]);
                float2 r1v = make_float2(d[f][2] + epi[(b0 + 8) * 128 + col],
                                         d[f][3] + epi[(b0 + 8) * 128 + col + 1]);
                *(float2*)(out + ((size_t)b0 * STEPS + t) * VOCAB + v0 + col) = r0v;
                *(float2*)(out + ((size_t)(b0 + 8) * STEPS + t) * VOCAB + v0 + col) = r1v;
            }
        }
    }
}

// ---------------- launch ----------------
extern "C" void kernel_launch(void* const* d_in, const int* in_sizes, int n_in,
                              void* d_out, int out_size) {
    const float* V      = (const float*)d_in[0];
    const int*   y      = (const int*)  d_in[1];
    const float* embed  = (const float*)d_in[2];
    const float* W_att  = (const float*)d_in[3];
    const float* U_att  = (const float*)d_in[4];
    const float* v_att  = (const float*)d_in[5];
    const float* W_ih   = (const float*)d_in[6];
    const float* W_hh   = (const float*)d_in[7];
    const float* b_ih   = (const float*)d_in[8];
    const float* b_hh   = (const float*)d_in[9];
    const float* W_inith = (const float*)d_in[10];
    const float* b_inith = (const float*)d_in[11];
    const float* W_initc = (const float*)d_in[12];
    const float* b_initc = (const float*)d_in[13];
    const float* W_proj  = (const float*)d_in[14];
    float* out = (float*)d_out;

    const int SMEM_GATES = (256 * 68 + 256 * 64) * sizeof(float);  // 135168
    const int SMEM_PROJ  = (128 * 68 + 128 * 64) * sizeof(float);  // 67584
    cudaFuncSetAttribute(k_gates, cudaFuncAttributeMaxDynamicSharedMemorySize, SMEM_GATES);
    cudaFuncSetAttribute(k_proj,  cudaFuncAttributeMaxDynamicSharedMemorySize, SMEM_PROJ);
    cudaFuncSetAttribute(k_logits_mma, cudaFuncAttributeMaxDynamicSharedMemorySize, SM_LOG);

    k_init_hc<<<B, 512>>>(V, W_inith, b_inith, W_initc, b_initc);
    k_uv<<<(B * N) / UV_ROWS, 256>>>(V, U_att);
    k_esplit<<<(VOCAB * EMB) / 512, 256>>>(embed);
    // hW(h0) for step 0 (hpb written too, overwritten before use)
    k_proj<<<dim3(8, 4), 256, SMEM_PROJ>>>(W_proj, W_att, b_ih, b_hh, 0, 0);
    k_split<<<B, 512>>>();

    for (int t = 0; t < STEPS; t++) {
        k_att<<<B, 256>>>(v_att, V);
        k_gates<<<dim3(32, 4), 256, SMEM_GATES>>>(embed, y, W_ih, W_hh, t);
        k_proj<<<dim3(8, 4), 256, SMEM_PROJ>>>(W_proj, W_att, b_ih, b_hh, t & 1, 1);
        k_split<<<B, 512>>>();
        k_logits_mma<<<VOCAB / 128, 256, SM_LOG>>>(out, t);
    }
}

// round 10
// speedup vs baseline: 1.1544x; 1.1303x over previous
#include <cuda_runtime.h>
#include <cuda_bf16.h>
#include <math.h>

#define B     64
#define N     196
#define TT    32
#define STEPS 31
#define VOCAB 32000
#define EMB   256
#define HDIM  512
#define VDIM  256
#define ATTD  256
#define G4    2048

// ---------------- scratch (device globals; no allocation) ----------------
__device__ float g_Uv[B * N * ATTD];
__device__ float g_h[B * HDIM];
__device__ float g_c[B * HDIM];
__device__ float g_ctx[B * VDIM];
__device__ float g_hW[B * ATTD];
__device__ float g_gpart[4 * B * G4];     // split-K partials for gates
__device__ __align__(16) __nv_bfloat16 g_hpb[128 * EMB];        // rows 0-63 hi, 64-127 lo
__device__ __align__(16) __nv_bfloat16 g_eh[(size_t)VOCAB * EMB];
__device__ __align__(16) __nv_bfloat16 g_el[(size_t)VOCAB * EMB];

__device__ __forceinline__ float sigmoidf_(float x) { return 1.f / (1.f + expf(-x)); }
__device__ __forceinline__ float tanh_fast(float x) {
    float y;
    asm("tanh.approx.f32 %0, %1;" : "=f"(y) : "f"(x));
    return y;
}

// ---------------- packed f32x2 FMA helpers (SIMT GEMMs) ----------------
typedef unsigned long long ull;
struct Acc44 { ull a[4][2]; };
__device__ __forceinline__ ull fma2(ull a, ull b, ull c) {
    ull d; asm("fma.rn.f32x2 %0, %1, %2, %3;" : "=l"(d) : "l"(a), "l"(b), "l"(c));
    return d;
}
__device__ __forceinline__ ull pack2(float x) {
    ull d; unsigned int xi = __float_as_uint(x);
    asm("mov.b64 %0, {%1, %1};" : "=l"(d) : "r"(xi));
    return d;
}
__device__ __forceinline__ void acc_zero(Acc44& A) {
    #pragma unroll
    for (int i = 0; i < 4; i++) { A.a[i][0] = 0ull; A.a[i][1] = 0ull; }
}
__device__ __forceinline__ void mma44(Acc44& A, float4 xf, ulonglong2 wf) {
    ull h;
    h = pack2(xf.x); A.a[0][0] = fma2(h, wf.x, A.a[0][0]); A.a[0][1] = fma2(h, wf.y, A.a[0][1]);
    h = pack2(xf.y); A.a[1][0] = fma2(h, wf.x, A.a[1][0]); A.a[1][1] = fma2(h, wf.y, A.a[1][1]);
    h = pack2(xf.z); A.a[2][0] = fma2(h, wf.x, A.a[2][0]); A.a[2][1] = fma2(h, wf.y, A.a[2][1]);
    h = pack2(xf.w); A.a[3][0] = fma2(h, wf.x, A.a[3][0]); A.a[3][1] = fma2(h, wf.y, A.a[3][1]);
}
__device__ __forceinline__ float4 unpack44(const Acc44& A, int i) {
    unsigned int l0, h0, l1, h1;
    asm("mov.b64 {%0,%1}, %2;" : "=r"(l0), "=r"(h0) : "l"(A.a[i][0]));
    asm("mov.b64 {%0,%1}, %2;" : "=r"(l1), "=r"(h1) : "l"(A.a[i][1]));
    return make_float4(__uint_as_float(l0), __uint_as_float(h0),
                       __uint_as_float(l1), __uint_as_float(h1));
}

__device__ __forceinline__ unsigned smem_u32(const void* p) {
    unsigned a;
    asm("{ .reg .u64 t; cvta.to.shared.u64 t, %1; cvt.u32.u64 %0, t; }" : "=r"(a) : "l"(p));
    return a;
}

// ---------------- init: feat_mean -> h0, c0 ----------------
__global__ void k_init_hc(const float* __restrict__ V,
                          const float* __restrict__ Wh, const float* __restrict__ bh,
                          const float* __restrict__ Wc, const float* __restrict__ bc) {
    int b = blockIdx.x, tid = threadIdx.x;
    __shared__ float fm[VDIM];
    if (tid < VDIM) {
        const float* vp = V + (size_t)b * N * VDIM + tid;
        float s = 0.f;
        for (int n = 0; n < N; n++) s += vp[(size_t)n * VDIM];
        fm[tid] = s * (1.f / (float)N);
    }
    __syncthreads();
    int j = tid;
    float ah = bh[j], ac = bc[j];
    #pragma unroll 4
    for (int v = 0; v < VDIM; v++) {
        float f = fm[v];
        ah += f * Wh[(size_t)v * HDIM + j];
        ac += f * Wc[(size_t)v * HDIM + j];
    }
    g_h[b * HDIM + j] = tanhf(ah);
    g_c[b * HDIM + j] = tanhf(ac);
}

// ---------------- Uv = V @ U_att (once) ----------------
#define UV_ROWS 16
__global__ void k_uv(const float* __restrict__ V, const float* __restrict__ U) {
    __shared__ float Vs[UV_ROWS * VDIM];
    int r0 = blockIdx.x * UV_ROWS;
    int tid = threadIdx.x;
    for (int i = tid; i < UV_ROWS * VDIM; i += 256)
        Vs[i] = V[(size_t)r0 * VDIM + i];
    __syncthreads();
    float acc[UV_ROWS];
    #pragma unroll
    for (int i = 0; i < UV_ROWS; i++) acc[i] = 0.f;
    int a = tid;
    #pragma unroll 4
    for (int v = 0; v < VDIM; v++) {
        float u = U[(size_t)v * ATTD + a];
        #pragma unroll
        for (int i = 0; i < UV_ROWS; i++) acc[i] += Vs[i * VDIM + v] * u;
    }
    #pragma unroll
    for (int i = 0; i < UV_ROWS; i++)
        g_Uv[(size_t)(r0 + i) * ATTD + a] = acc[i];
}

// ---------------- embed -> bf16 hi/lo (once) ----------------
__global__ void k_esplit(const float* __restrict__ e) {
    size_t i = ((size_t)blockIdx.x * 256 + threadIdx.x) * 2;
    float2 v = *(const float2*)(e + i);
    __nv_bfloat16 h0 = __float2bfloat16(v.x);
    __nv_bfloat16 h1 = __float2bfloat16(v.y);
    __nv_bfloat16 l0 = __float2bfloat16(v.x - __bfloat162float(h0));
    __nv_bfloat16 l1 = __float2bfloat16(v.y - __bfloat162float(h1));
    *(__nv_bfloat162*)(g_eh + i) = __nv_bfloat162(h0, h1);
    *(__nv_bfloat162*)(g_el + i) = __nv_bfloat162(l0, l1);
}

// ---------------- fused attention: energies + softmax + ctx ----------------
__global__ void k_att(const float* __restrict__ vatt, const float* __restrict__ V) {
    int b = blockIdx.x, tid = threadIdx.x;
    __shared__ float hWs[ATTD];
    __shared__ float vs[ATTD];
    __shared__ float es[256];
    __shared__ float red[256];
    hWs[tid] = g_hW[b * ATTD + tid];
    vs[tid] = vatt[tid];
    __syncthreads();
    int warp = tid >> 5, lane = tid & 31;
    for (int n = warp; n < N; n += 8) {
        const float* uv = g_Uv + (size_t)(b * N + n) * ATTD;
        float p = 0.f;
        #pragma unroll
        for (int j = 0; j < 8; j++) {
            int a = lane + 32 * j;
            p += tanh_fast(hWs[a] + uv[a]) * vs[a];
        }
        #pragma unroll
        for (int off = 16; off > 0; off >>= 1)
            p += __shfl_down_sync(0xffffffffu, p, off);
        if (lane == 0) es[n] = p;
    }
    __syncthreads();
    float v = (tid < N) ? es[tid] : -INFINITY;
    red[tid] = v;
    __syncthreads();
    for (int s = 128; s > 0; s >>= 1) {
        if (tid < s) red[tid] = fmaxf(red[tid], red[tid + s]);
        __syncthreads();
    }
    float mx = red[0];
    __syncthreads();
    float ex = (tid < N) ? expf(v - mx) : 0.f;
    red[tid] = ex;
    __syncthreads();
    for (int s = 128; s > 0; s >>= 1) {
        if (tid < s) red[tid] += red[tid + s];
        __syncthreads();
    }
    float inv = 1.f / red[0];
    __syncthreads();
    if (tid < N) es[tid] = ex * inv;
    __syncthreads();
    const float* vp = V + (size_t)b * N * VDIM + tid;
    float acc = 0.f;
    #pragma unroll 4
    for (int n = 0; n < N; n++) acc += es[n] * vp[(size_t)n * VDIM];
    g_ctx[b * VDIM + tid] = acc;
}

// ---------------- gates GEMM: [64,1024] @ [1024,2048], split-K ----------------
__global__ void k_gates(const float* __restrict__ embed, const int* __restrict__ y,
                        const float* __restrict__ Wih, const float* __restrict__ Whh, int t) {
    extern __shared__ float sm[];
    float* Xs = sm;
    float* Ws = sm + 256 * 68;
    int j0 = blockIdx.x * 64;
    int kc = blockIdx.y;
    int tid = threadIdx.x;

    for (int idx = tid; idx < B * 256; idx += 256) {
        int kk = idx & 255, bb = idx >> 8;
        float x;
        if (kc == 0)      x = embed[(size_t)y[bb * TT + t] * EMB + kk];
        else if (kc == 1) x = g_ctx[bb * VDIM + kk];
        else if (kc == 2) x = g_h[bb * HDIM + kk];
        else              x = g_h[bb * HDIM + 256 + kk];
        Xs[kk * 68 + bb] = x;
    }
    const float* W = (kc < 2) ? (Wih + (size_t)(kc * 256) * G4)
                              : (Whh + (size_t)((kc - 2) * 256) * G4);
    for (int idx = tid; idx < 256 * 64; idx += 256) {
        int kk = idx >> 6, jj = idx & 63;
        Ws[idx] = W[(size_t)kk * G4 + j0 + jj];
    }
    __syncthreads();

    int tx = tid & 15, ty = tid >> 4;
    Acc44 A; acc_zero(A);
    #pragma unroll 4
    for (int kk = 0; kk < 256; kk++) {
        float4 xf = *(const float4*)&Xs[kk * 68 + ty * 4];
        ulonglong2 wf = *(const ulonglong2*)&Ws[kk * 64 + tx * 4];
        mma44(A, xf, wf);
    }
    float* gp = g_gpart + (size_t)kc * B * G4;
    #pragma unroll
    for (int i = 0; i < 4; i++) {
        int bb = ty * 4 + i;
        *(float4*)&gp[(size_t)bb * G4 + j0 + tx * 4] = unpack44(A, i);
    }
}

// ---------------- LSTM update (in-place c, coalesced partial reads) ----------------
// grid = B, block = 512
__global__ void k_lstm(const float* __restrict__ bih, const float* __restrict__ bhh) {
    int b = blockIdx.x, j = threadIdx.x;
    float gi = bih[j]        + bhh[j];
    float gf = bih[512 + j]  + bhh[512 + j];
    float gg = bih[1024 + j] + bhh[1024 + j];
    float go = bih[1536 + j] + bhh[1536 + j];
    #pragma unroll
    for (int kc = 0; kc < 4; kc++) {
        const float* gp = g_gpart + (size_t)kc * B * G4 + (size_t)b * G4;
        gi += gp[j]; gf += gp[512 + j]; gg += gp[1024 + j]; go += gp[1536 + j];
    }
    float c = sigmoidf_(gf) * g_c[b * HDIM + j] + sigmoidf_(gi) * tanhf(gg);
    float h = sigmoidf_(go) * tanhf(c);
    g_c[b * HDIM + j] = c;
    g_h[b * HDIM + j] = h;
}

// ---------------- proj: [hp|hW] = h @ [Wproj|Watt], full-K, direct hi/lo write ----------------
// grid = 32 (j tiles of 16), block = 256, dyn smem = 43008
__global__ void k_proj2(const float* __restrict__ Wproj, const float* __restrict__ Watt) {
    extern __shared__ float sm[];
    float* Xs = sm;               // [128 kk][68 pad] h^T chunk (bb fastest)
    float* Ws = sm + 128 * 68;    // [128 kk][16 jj]
    int j0 = blockIdx.x * 16;
    int tid = threadIdx.x;
    const float* W = (j0 < 256) ? (Wproj + j0) : (Watt + (j0 - 256));

    int tx = tid & 3, ty = tid >> 2;   // ty = batch row 0..63, tx = j quad
    float acc[4] = {0.f, 0.f, 0.f, 0.f};

    #pragma unroll
    for (int kc = 0; kc < 4; kc++) {
        for (int idx = tid; idx < B * 128; idx += 256) {
            int kk = idx & 127, bb = idx >> 7;
            Xs[kk * 68 + bb] = g_h[bb * HDIM + kc * 128 + kk];
        }
        for (int idx = tid; idx < 128 * 16; idx += 256) {
            int kk = idx >> 4, jj = idx & 15;
            Ws[idx] = W[(size_t)(kc * 128 + kk) * 256 + jj];
        }
        __syncthreads();
        #pragma unroll 8
        for (int kk = 0; kk < 128; kk++) {
            float x = Xs[kk * 68 + ty];
            float4 w = *(const float4*)&Ws[kk * 16 + tx * 4];
            acc[0] += x * w.x; acc[1] += x * w.y; acc[2] += x * w.z; acc[3] += x * w.w;
        }
        __syncthreads();
    }

    int j = j0 + tx * 4;
    if (j0 < 256) {
        #pragma unroll
        for (int i = 0; i < 4; i++) {
            float s = acc[i];
            __nv_bfloat16 hi = __float2bfloat16(s);
            __nv_bfloat16 lo = __float2bfloat16(s - __bfloat162float(hi));
            g_hpb[ty * EMB + j + i] = hi;
            g_hpb[(64 + ty) * EMB + j + i] = lo;
        }
    } else {
        #pragma unroll
        for (int i = 0; i < 4; i++)
            g_hW[ty * ATTD + (j - 256) + i] = acc[i];
    }
}

// ---------------- logits via mma.sync bf16 hi/lo split (ldmatrix B, AlBl skipped) ----------------
// grid = 250, block = 256 (8 warps: 4 m-rows x 2 n-cols), dyn smem = 102400
#define SA  0
#define SBH 32768
#define SBL (SBH + 34816)
#define SM_LOG (SBL + 34816)   // 102400

__global__ void __launch_bounds__(256, 2) k_logits_mma(float* __restrict__ out, int t) {
    extern __shared__ char smc[];
    const unsigned sb = smem_u32(smc);
    int tid = threadIdx.x;
    int wid = tid >> 5, lane = tid & 31;
    int wr = wid & 3, wc = wid >> 2;        // warp tile: rows wr*32.., cols wc*64..
    int v0 = blockIdx.x * 128;
    bool hiwarp = (wr < 2);                  // rows are hi(hp): needs Bh AND Bl

    float d[16][4];                          // f = mi*8 + ng
    #pragma unroll
    for (int f = 0; f < 16; f++) { d[f][0] = d[f][1] = d[f][2] = d[f][3] = 0.f; }

    // B ldmatrix lane->address components (fixed per thread)
    int bmat = lane >> 3, brow = lane & 7;
    int bn_local = ((bmat >> 1) << 3) + brow;   // 0..15 within a 16-n pair group
    unsigned bkoff = (unsigned)((bmat & 1) << 3) * 2;  // 0 or 16 bytes

    #pragma unroll
    for (int kc = 0; kc < 2; kc++) {
        // A chunk: g_hpb[m][kc*128..+127] -> swizzled smem
        for (int i = tid; i < 2048; i += 256) {
            int m = i >> 4, u = i & 15;
            *(uint4*)(smc + SA + m * 256 + ((u ^ (m & 7)) << 4)) =
                *(const uint4*)((const char*)g_hpb + (size_t)m * 512 + kc * 256 + u * 16);
        }
        // B chunks (hi & lo), rows padded to 272B
        for (int i = tid; i < 2048; i += 256) {
            int n = i >> 4, u = i & 15;
            size_t go = (size_t)(v0 + n) * 512 + kc * 256 + u * 16;
            *(uint4*)(smc + SBH + n * 272 + u * 16) = *(const uint4*)((const char*)g_eh + go);
            *(uint4*)(smc + SBL + n * 272 + u * 16) = *(const uint4*)((const char*)g_el + go);
        }
        __syncthreads();

        #pragma unroll
        for (int ks = 0; ks < 8; ks++) {
            // A fragments (2 per warp) via ldmatrix.x4
            unsigned a[2][4];
            #pragma unroll
            for (int mi = 0; mi < 2; mi++) {
                int m = wr * 32 + mi * 16 + ((lane >> 3) & 1) * 8 + (lane & 7);
                int u = ks * 2 + (lane >> 4);
                unsigned addr = sb + SA + m * 256 + ((u ^ (m & 7)) << 4);
                asm volatile(
                    "ldmatrix.sync.aligned.m8n8.x4.shared.b16 {%0,%1,%2,%3}, [%4];"
                    : "=r"(a[mi][0]), "=r"(a[mi][1]), "=r"(a[mi][2]), "=r"(a[mi][3])
                    : "r"(addr));
            }
            unsigned bko = (unsigned)(ks * 32) + bkoff;   // ks*16 k-elems * 2B + half
            #pragma unroll
            for (int np = 0; np < 4; np++) {              // 4 pairs of n8 groups
                unsigned brow_addr = sb + SBH +
                    (unsigned)((wc * 64 + np * 16 + bn_local) * 272) + bko;
                unsigned bh[4];
                asm volatile(
                    "ldmatrix.sync.aligned.m8n8.x4.shared.b16 {%0,%1,%2,%3}, [%4];"
                    : "=r"(bh[0]), "=r"(bh[1]), "=r"(bh[2]), "=r"(bh[3])
                    : "r"(brow_addr));
                #pragma unroll
                for (int half = 0; half < 2; half++) {
                    int f0 = np * 2 + half;
                    #pragma unroll
                    for (int mi = 0; mi < 2; mi++) {
                        int f = mi * 8 + f0;
                        asm volatile(
                            "mma.sync.aligned.m16n8k16.row.col.f32.bf16.bf16.f32 "
                            "{%0,%1,%2,%3}, {%4,%5,%6,%7}, {%8,%9}, {%0,%1,%2,%3};"
                            : "+f"(d[f][0]), "+f"(d[f][1]), "+f"(d[f][2]), "+f"(d[f][3])
                            : "r"(a[mi][0]), "r"(a[mi][1]), "r"(a[mi][2]), "r"(a[mi][3]),
                              "r"(bh[half * 2]), "r"(bh[half * 2 + 1]));
                    }
                }
                if (hiwarp) {
                    unsigned blo_addr = brow_addr + (SBL - SBH);
                    unsigned bl[4];
                    asm volatile(
                        "ldmatrix.sync.aligned.m8n8.x4.shared.b16 {%0,%1,%2,%3}, [%4];"
                        : "=r"(bl[0]), "=r"(bl[1]), "=r"(bl[2]), "=r"(bl[3])
                        : "r"(blo_addr));
                    #pragma unroll
                    for (int half = 0; half < 2; half++) {
                        int f0 = np * 2 + half;
                        #pragma unroll
                        for (int mi = 0; mi < 2; mi++) {
                            int f = mi * 8 + f0;
                            asm volatile(
                                "mma.sync.aligned.m16n8k16.row.col.f32.bf16.bf16.f32 "
                                "{%0,%1,%2,%3}, {%4,%5,%6,%7}, {%8,%9}, {%0,%1,%2,%3};"
                                : "+f"(d[f][0]), "+f"(d[f][1]), "+f"(d[f][2]), "+f"(d[f][3])
                                : "r"(a[mi][0]), "r"(a[mi][1]), "r"(a[mi][2]), "r"(a[mi][3]),
                                  "r"(bl[half * 2]), "r"(bl[half * 2 + 1]));
                        }
                    }
                }
            }
        }
        __syncthreads();
    }

    // epilogue: lo rows (m>=64, = Al@Bh) -> smem; hi rows add + store
    float* epi = (float*)(smc + SA);        // [64 m][128 n]
    if (wr >= 2) {
        #pragma unroll
        for (int mi = 0; mi < 2; mi++) {
            int r0 = (wr - 2) * 32 + mi * 16 + (lane >> 2);
            #pragma unroll
            for (int nf = 0; nf < 8; nf++) {
                int f = mi * 8 + nf;
                int col = wc * 64 + nf * 8 + (lane & 3) * 2;
                epi[r0 * 128 + col]           = d[f][0];
                epi[r0 * 128 + col + 1]       = d[f][1];
                epi[(r0 + 8) * 128 + col]     = d[f][2];
                epi[(r0 + 8) * 128 + col + 1] = d[f][3];
            }
        }
    }
    __syncthreads();
    if (wr < 2) {
        #pragma unroll
        for (int mi = 0; mi < 2; mi++) {
            int b0 = wr * 32 + mi * 16 + (lane >> 2);
            #pragma unroll
            for (int nf = 0; nf < 8; nf++) {
                int f = mi * 8 + nf;
                int col = wc * 64 + nf * 8 + (lane & 3) * 2;
                float2 r0v = make_float2(d[f][0] + epi[b0 * 128 + col],
                                         d[f][1] + epi[b0 * 128 + col + 1]);
                float2 r1v = make_float2(d[f][2] + epi[(b0 + 8) * 128 + col],
                                         d[f][3] + epi[(b0 + 8) * 128 + col + 1]);
                *(float2*)(out + ((size_t)b0 * STEPS + t) * VOCAB + v0 + col) = r0v;
                *(float2*)(out + ((size_t)(b0 + 8) * STEPS + t) * VOCAB + v0 + col) = r1v;
            }
        }
    }
}

// ---------------- launch ----------------
extern "C" void kernel_launch(void* const* d_in, const int* in_sizes, int n_in,
                              void* d_out, int out_size) {
    const float* V      = (const float*)d_in[0];
    const int*   y      = (const int*)  d_in[1];
    const float* embed  = (const float*)d_in[2];
    const float* W_att  = (const float*)d_in[3];
    const float* U_att  = (const float*)d_in[4];
    const float* v_att  = (const float*)d_in[5];
    const float* W_ih   = (const float*)d_in[6];
    const float* W_hh   = (const float*)d_in[7];
    const float* b_ih   = (const float*)d_in[8];
    const float* b_hh   = (const float*)d_in[9];
    const float* W_inith = (const float*)d_in[10];
    const float* b_inith = (const float*)d_in[11];
    const float* W_initc = (const float*)d_in[12];
    const float* b_initc = (const float*)d_in[13];
    const float* W_proj  = (const float*)d_in[14];
    float* out = (float*)d_out;

    const int SMEM_GATES = (256 * 68 + 256 * 64) * sizeof(float);  // 135168
    const int SMEM_PROJ  = (128 * 68 + 128 * 16) * sizeof(float);  // 43008
    cudaFuncSetAttribute(k_gates, cudaFuncAttributeMaxDynamicSharedMemorySize, SMEM_GATES);
    cudaFuncSetAttribute(k_proj2, cudaFuncAttributeMaxDynamicSharedMemorySize, SMEM_PROJ);
    cudaFuncSetAttribute(k_logits_mma, cudaFuncAttributeMaxDynamicSharedMemorySize, SM_LOG);

    k_init_hc<<<B, 512>>>(V, W_inith, b_inith, W_initc, b_initc);
    k_uv<<<(B * N) / UV_ROWS, 256>>>(V, U_att);
    k_esplit<<<(VOCAB * EMB) / 512, 256>>>(embed);
    k_proj2<<<32, 256, SMEM_PROJ>>>(W_proj, W_att);   // hW(h0); hpb(h0) unused

    for (int t = 0; t < STEPS; t++) {
        k_att<<<B, 256>>>(v_att, V);
        k_gates<<<dim3(32, 4), 256, SMEM_GATES>>>(embed, y, W_ih, W_hh, t);
        k_lstm<<<B, 512>>>(b_ih, b_hh);
        k_proj2<<<32, 256, SMEM_PROJ>>>(W_proj, W_att);
        k_logits_mma<<<VOCAB / 128, 256, SM_LOG>>>(out, t);
    }
}

// round 11
// speedup vs baseline: 1.3094x; 1.1343x over previous
#include <cuda_runtime.h>
#include <cuda_bf16.h>
#include <math.h>

#define B     64
#define N     196
#define TT    32
#define STEPS 31
#define VOCAB 32000
#define EMB   256
#define HDIM  512
#define VDIM  256
#define ATTD  256
#define G4    2048

// ---------------- scratch (device globals; no allocation) ----------------
__device__ float g_Uv[B * N * ATTD];
__device__ float g_h[B * HDIM];
__device__ float g_c[B * HDIM];
__device__ float g_ctx[B * VDIM];
__device__ float g_hW[B * ATTD];
__device__ float g_gpart[4 * B * G4];     // split-K partials for gates
__device__ __align__(16) __nv_bfloat16 g_hpb[128 * EMB];        // rows 0-63 hi, 64-127 lo
__device__ __align__(16) __nv_bfloat16 g_eh[(size_t)VOCAB * EMB];
__device__ __align__(16) __nv_bfloat16 g_el[(size_t)VOCAB * EMB];

__device__ __forceinline__ float sigmoidf_(float x) { return 1.f / (1.f + expf(-x)); }
__device__ __forceinline__ float tanh_fast(float x) {
    float y;
    asm("tanh.approx.f32 %0, %1;" : "=f"(y) : "f"(x));
    return y;
}

// ---------------- packed f32x2 FMA helpers (SIMT GEMMs) ----------------
typedef unsigned long long ull;
struct Acc44 { ull a[4][2]; };
__device__ __forceinline__ ull fma2(ull a, ull b, ull c) {
    ull d; asm("fma.rn.f32x2 %0, %1, %2, %3;" : "=l"(d) : "l"(a), "l"(b), "l"(c));
    return d;
}
__device__ __forceinline__ ull pack2(float x) {
    ull d; unsigned int xi = __float_as_uint(x);
    asm("mov.b64 %0, {%1, %1};" : "=l"(d) : "r"(xi));
    return d;
}
__device__ __forceinline__ void acc_zero(Acc44& A) {
    #pragma unroll
    for (int i = 0; i < 4; i++) { A.a[i][0] = 0ull; A.a[i][1] = 0ull; }
}
__device__ __forceinline__ void mma44(Acc44& A, float4 xf, ulonglong2 wf) {
    ull h;
    h = pack2(xf.x); A.a[0][0] = fma2(h, wf.x, A.a[0][0]); A.a[0][1] = fma2(h, wf.y, A.a[0][1]);
    h = pack2(xf.y); A.a[1][0] = fma2(h, wf.x, A.a[1][0]); A.a[1][1] = fma2(h, wf.y, A.a[1][1]);
    h = pack2(xf.z); A.a[2][0] = fma2(h, wf.x, A.a[2][0]); A.a[2][1] = fma2(h, wf.y, A.a[2][1]);
    h = pack2(xf.w); A.a[3][0] = fma2(h, wf.x, A.a[3][0]); A.a[3][1] = fma2(h, wf.y, A.a[3][1]);
}
__device__ __forceinline__ float4 unpack44(const Acc44& A, int i) {
    unsigned int l0, h0, l1, h1;
    asm("mov.b64 {%0,%1}, %2;" : "=r"(l0), "=r"(h0) : "l"(A.a[i][0]));
    asm("mov.b64 {%0,%1}, %2;" : "=r"(l1), "=r"(h1) : "l"(A.a[i][1]));
    return make_float4(__uint_as_float(l0), __uint_as_float(h0),
                       __uint_as_float(l1), __uint_as_float(h1));
}

__device__ __forceinline__ unsigned smem_u32(const void* p) {
    unsigned a;
    asm("{ .reg .u64 t; cvta.to.shared.u64 t, %1; cvt.u32.u64 %0, t; }" : "=r"(a) : "l"(p));
    return a;
}

// ---------------- init: feat_mean -> h0, c0 ----------------
__global__ void k_init_hc(const float* __restrict__ V,
                          const float* __restrict__ Wh, const float* __restrict__ bh,
                          const float* __restrict__ Wc, const float* __restrict__ bc) {
    int b = blockIdx.x, tid = threadIdx.x;
    __shared__ float fm[VDIM];
    if (tid < VDIM) {
        const float* vp = V + (size_t)b * N * VDIM + tid;
        float s = 0.f;
        for (int n = 0; n < N; n++) s += vp[(size_t)n * VDIM];
        fm[tid] = s * (1.f / (float)N);
    }
    __syncthreads();
    int j = tid;
    float ah = bh[j], ac = bc[j];
    #pragma unroll 4
    for (int v = 0; v < VDIM; v++) {
        float f = fm[v];
        ah += f * Wh[(size_t)v * HDIM + j];
        ac += f * Wc[(size_t)v * HDIM + j];
    }
    g_h[b * HDIM + j] = tanhf(ah);
    g_c[b * HDIM + j] = tanhf(ac);
}

// ---------------- hW(h0) for step 0: coalesced GEMV per batch ----------------
// grid = B, block = 256
__global__ void k_hw0(const float* __restrict__ Watt) {
    int b = blockIdx.x, j = threadIdx.x;
    __shared__ float hs[HDIM];
    hs[j] = g_h[b * HDIM + j];
    hs[j + 256] = g_h[b * HDIM + 256 + j];
    __syncthreads();
    float acc = 0.f;
    #pragma unroll 8
    for (int k = 0; k < HDIM; k++) acc += hs[k] * Watt[(size_t)k * ATTD + j];
    g_hW[b * ATTD + j] = acc;
}

// ---------------- Uv = V @ U_att (once) ----------------
#define UV_ROWS 16
__global__ void k_uv(const float* __restrict__ V, const float* __restrict__ U) {
    __shared__ float Vs[UV_ROWS * VDIM];
    int r0 = blockIdx.x * UV_ROWS;
    int tid = threadIdx.x;
    for (int i = tid; i < UV_ROWS * VDIM; i += 256)
        Vs[i] = V[(size_t)r0 * VDIM + i];
    __syncthreads();
    float acc[UV_ROWS];
    #pragma unroll
    for (int i = 0; i < UV_ROWS; i++) acc[i] = 0.f;
    int a = tid;
    #pragma unroll 4
    for (int v = 0; v < VDIM; v++) {
        float u = U[(size_t)v * ATTD + a];
        #pragma unroll
        for (int i = 0; i < UV_ROWS; i++) acc[i] += Vs[i * VDIM + v] * u;
    }
    #pragma unroll
    for (int i = 0; i < UV_ROWS; i++)
        g_Uv[(size_t)(r0 + i) * ATTD + a] = acc[i];
}

// ---------------- embed -> bf16 hi/lo (once) ----------------
__global__ void k_esplit(const float* __restrict__ e) {
    size_t i = ((size_t)blockIdx.x * 256 + threadIdx.x) * 2;
    float2 v = *(const float2*)(e + i);
    __nv_bfloat16 h0 = __float2bfloat16(v.x);
    __nv_bfloat16 h1 = __float2bfloat16(v.y);
    __nv_bfloat16 l0 = __float2bfloat16(v.x - __bfloat162float(h0));
    __nv_bfloat16 l1 = __float2bfloat16(v.y - __bfloat162float(h1));
    *(__nv_bfloat162*)(g_eh + i) = __nv_bfloat162(h0, h1);
    *(__nv_bfloat162*)(g_el + i) = __nv_bfloat162(l0, l1);
}

// ---------------- fused attention: energies + softmax + ctx ----------------
__global__ void k_att(const float* __restrict__ vatt, const float* __restrict__ V) {
    int b = blockIdx.x, tid = threadIdx.x;
    __shared__ float hWs[ATTD];
    __shared__ float vs[ATTD];
    __shared__ float es[256];
    __shared__ float red[256];
    hWs[tid] = g_hW[b * ATTD + tid];
    vs[tid] = vatt[tid];
    __syncthreads();
    int warp = tid >> 5, lane = tid & 31;
    for (int n = warp; n < N; n += 8) {
        const float* uv = g_Uv + (size_t)(b * N + n) * ATTD;
        float p = 0.f;
        #pragma unroll
        for (int j = 0; j < 8; j++) {
            int a = lane + 32 * j;
            p += tanh_fast(hWs[a] + uv[a]) * vs[a];
        }
        #pragma unroll
        for (int off = 16; off > 0; off >>= 1)
            p += __shfl_down_sync(0xffffffffu, p, off);
        if (lane == 0) es[n] = p;
    }
    __syncthreads();
    float v = (tid < N) ? es[tid] : -INFINITY;
    red[tid] = v;
    __syncthreads();
    for (int s = 128; s > 0; s >>= 1) {
        if (tid < s) red[tid] = fmaxf(red[tid], red[tid + s]);
        __syncthreads();
    }
    float mx = red[0];
    __syncthreads();
    float ex = (tid < N) ? expf(v - mx) : 0.f;
    red[tid] = ex;
    __syncthreads();
    for (int s = 128; s > 0; s >>= 1) {
        if (tid < s) red[tid] += red[tid + s];
        __syncthreads();
    }
    float inv = 1.f / red[0];
    __syncthreads();
    if (tid < N) es[tid] = ex * inv;
    __syncthreads();
    const float* vp = V + (size_t)b * N * VDIM + tid;
    float acc = 0.f;
    #pragma unroll 4
    for (int n = 0; n < N; n++) acc += es[n] * vp[(size_t)n * VDIM];
    g_ctx[b * VDIM + tid] = acc;
}

// ---------------- gates GEMM: [64,1024] @ [1024,2048], split-K ----------------
__global__ void k_gates(const float* __restrict__ embed, const int* __restrict__ y,
                        const float* __restrict__ Wih, const float* __restrict__ Whh, int t) {
    extern __shared__ float sm[];
    float* Xs = sm;
    float* Ws = sm + 256 * 68;
    int j0 = blockIdx.x * 64;
    int kc = blockIdx.y;
    int tid = threadIdx.x;

    for (int idx = tid; idx < B * 256; idx += 256) {
        int kk = idx & 255, bb = idx >> 8;
        float x;
        if (kc == 0)      x = embed[(size_t)y[bb * TT + t] * EMB + kk];
        else if (kc == 1) x = g_ctx[bb * VDIM + kk];
        else if (kc == 2) x = g_h[bb * HDIM + kk];
        else              x = g_h[bb * HDIM + 256 + kk];
        Xs[kk * 68 + bb] = x;
    }
    const float* W = (kc < 2) ? (Wih + (size_t)(kc * 256) * G4)
                              : (Whh + (size_t)((kc - 2) * 256) * G4);
    for (int idx = tid; idx < 256 * 64; idx += 256) {
        int kk = idx >> 6, jj = idx & 63;
        Ws[idx] = W[(size_t)kk * G4 + j0 + jj];
    }
    __syncthreads();

    int tx = tid & 15, ty = tid >> 4;
    Acc44 A; acc_zero(A);
    #pragma unroll 4
    for (int kk = 0; kk < 256; kk++) {
        float4 xf = *(const float4*)&Xs[kk * 68 + ty * 4];
        ulonglong2 wf = *(const ulonglong2*)&Ws[kk * 64 + tx * 4];
        mma44(A, xf, wf);
    }
    float* gp = g_gpart + (size_t)kc * B * G4;
    #pragma unroll
    for (int i = 0; i < 4; i++) {
        int bb = ty * 4 + i;
        *(float4*)&gp[(size_t)bb * G4 + j0 + tx * 4] = unpack44(A, i);
    }
}

// ---------------- fused LSTM update + proj GEMV ----------------
// grid = B, block = 512. Thread j: LSTM for (b,j); then per-thread dot for
// hp (j<256, -> bf16 hi/lo) or hW (j>=256). W reads fully coalesced, L2-hot.
__global__ void k_lstm_proj(const float* __restrict__ bih, const float* __restrict__ bhh,
                            const float* __restrict__ Wproj, const float* __restrict__ Watt) {
    int b = blockIdx.x, j = threadIdx.x;
    __shared__ float hs[HDIM];

    float gi = bih[j]        + bhh[j];
    float gf = bih[512 + j]  + bhh[512 + j];
    float gg = bih[1024 + j] + bhh[1024 + j];
    float go = bih[1536 + j] + bhh[1536 + j];
    #pragma unroll
    for (int kc = 0; kc < 4; kc++) {
        const float* gp = g_gpart + (size_t)kc * B * G4 + (size_t)b * G4;
        gi += gp[j]; gf += gp[512 + j]; gg += gp[1024 + j]; go += gp[1536 + j];
    }
    float c = sigmoidf_(gf) * g_c[b * HDIM + j] + sigmoidf_(gi) * tanhf(gg);
    float h = sigmoidf_(go) * tanhf(c);
    g_c[b * HDIM + j] = c;
    g_h[b * HDIM + j] = h;
    hs[j] = h;
    __syncthreads();

    const float* W = (j < 256) ? (Wproj + j) : (Watt + (j - 256));
    float acc = 0.f;
    #pragma unroll 8
    for (int k = 0; k < HDIM; k++) acc += hs[k] * W[(size_t)k * 256];

    if (j < 256) {
        __nv_bfloat16 hi = __float2bfloat16(acc);
        __nv_bfloat16 lo = __float2bfloat16(acc - __bfloat162float(hi));
        g_hpb[b * EMB + j] = hi;
        g_hpb[(64 + b) * EMB + j] = lo;
    } else {
        g_hW[b * ATTD + (j - 256)] = acc;
    }
}

// ---------------- logits via mma.sync bf16 hi/lo split (ldmatrix B, AlBl skipped) ----------------
// grid = 250, block = 256 (8 warps: 4 m-rows x 2 n-cols), dyn smem = 102400
#define SA  0
#define SBH 32768
#define SBL (SBH + 34816)
#define SM_LOG (SBL + 34816)   // 102400

__global__ void __launch_bounds__(256, 2) k_logits_mma(float* __restrict__ out, int t) {
    extern __shared__ char smc[];
    const unsigned sb = smem_u32(smc);
    int tid = threadIdx.x;
    int wid = tid >> 5, lane = tid & 31;
    int wr = wid & 3, wc = wid >> 2;        // warp tile: rows wr*32.., cols wc*64..
    int v0 = blockIdx.x * 128;
    bool hiwarp = (wr < 2);                  // rows are hi(hp): needs Bh AND Bl

    float d[16][4];                          // f = mi*8 + ng
    #pragma unroll
    for (int f = 0; f < 16; f++) { d[f][0] = d[f][1] = d[f][2] = d[f][3] = 0.f; }

    // B ldmatrix lane->address components (fixed per thread)
    int bmat = lane >> 3, brow = lane & 7;
    int bn_local = ((bmat >> 1) << 3) + brow;   // 0..15 within a 16-n pair group
    unsigned bkoff = (unsigned)((bmat & 1) << 3) * 2;  // 0 or 16 bytes

    #pragma unroll
    for (int kc = 0; kc < 2; kc++) {
        // A chunk: g_hpb[m][kc*128..+127] -> swizzled smem
        for (int i = tid; i < 2048; i += 256) {
            int m = i >> 4, u = i & 15;
            *(uint4*)(smc + SA + m * 256 + ((u ^ (m & 7)) << 4)) =
                *(const uint4*)((const char*)g_hpb + (size_t)m * 512 + kc * 256 + u * 16);
        }
        // B chunks (hi & lo), rows padded to 272B
        for (int i = tid; i < 2048; i += 256) {
            int n = i >> 4, u = i & 15;
            size_t go = (size_t)(v0 + n) * 512 + kc * 256 + u * 16;
            *(uint4*)(smc + SBH + n * 272 + u * 16) = *(const uint4*)((const char*)g_eh + go);
            *(uint4*)(smc + SBL + n * 272 + u * 16) = *(const uint4*)((const char*)g_el + go);
        }
        __syncthreads();

        #pragma unroll
        for (int ks = 0; ks < 8; ks++) {
            // A fragments (2 per warp) via ldmatrix.x4
            unsigned a[2][4];
            #pragma unroll
            for (int mi = 0; mi < 2; mi++) {
                int m = wr * 32 + mi * 16 + ((lane >> 3) & 1) * 8 + (lane & 7);
                int u = ks * 2 + (lane >> 4);
                unsigned addr = sb + SA + m * 256 + ((u ^ (m & 7)) << 4);
                asm volatile(
                    "ldmatrix.sync.aligned.m8n8.x4.shared.b16 {%0,%1,%2,%3}, [%4];"
                    : "=r"(a[mi][0]), "=r"(a[mi][1]), "=r"(a[mi][2]), "=r"(a[mi][3])
                    : "r"(addr));
            }
            unsigned bko = (unsigned)(ks * 32) + bkoff;   // ks*16 k-elems * 2B + half
            #pragma unroll
            for (int np = 0; np < 4; np++) {              // 4 pairs of n8 groups
                unsigned brow_addr = sb + SBH +
                    (unsigned)((wc * 64 + np * 16 + bn_local) * 272) + bko;
                unsigned bh[4];
                asm volatile(
                    "ldmatrix.sync.aligned.m8n8.x4.shared.b16 {%0,%1,%2,%3}, [%4];"
                    : "=r"(bh[0]), "=r"(bh[1]), "=r"(bh[2]), "=r"(bh[3])
                    : "r"(brow_addr));
                #pragma unroll
                for (int half = 0; half < 2; half++) {
                    int f0 = np * 2 + half;
                    #pragma unroll
                    for (int mi = 0; mi < 2; mi++) {
                        int f = mi * 8 + f0;
                        asm volatile(
                            "mma.sync.aligned.m16n8k16.row.col.f32.bf16.bf16.f32 "
                            "{%0,%1,%2,%3}, {%4,%5,%6,%7}, {%8,%9}, {%0,%1,%2,%3};"
                            : "+f"(d[f][0]), "+f"(d[f][1]), "+f"(d[f][2]), "+f"(d[f][3])
                            : "r"(a[mi][0]), "r"(a[mi][1]), "r"(a[mi][2]), "r"(a[mi][3]),
                              "r"(bh[half * 2]), "r"(bh[half * 2 + 1]));
                    }
                }
                if (hiwarp) {
                    unsigned blo_addr = brow_addr + (SBL - SBH);
                    unsigned bl[4];
                    asm volatile(
                        "ldmatrix.sync.aligned.m8n8.x4.shared.b16 {%0,%1,%2,%3}, [%4];"
                        : "=r"(bl[0]), "=r"(bl[1]), "=r"(bl[2]), "=r"(bl[3])
                        : "r"(blo_addr));
                    #pragma unroll
                    for (int half = 0; half < 2; half++) {
                        int f0 = np * 2 + half;
                        #pragma unroll
                        for (int mi = 0; mi < 2; mi++) {
                            int f = mi * 8 + f0;
                            asm volatile(
                                "mma.sync.aligned.m16n8k16.row.col.f32.bf16.bf16.f32 "
                                "{%0,%1,%2,%3}, {%4,%5,%6,%7}, {%8,%9}, {%0,%1,%2,%3};"
                                : "+f"(d[f][0]), "+f"(d[f][1]), "+f"(d[f][2]), "+f"(d[f][3])
                                : "r"(a[mi][0]), "r"(a[mi][1]), "r"(a[mi][2]), "r"(a[mi][3]),
                                  "r"(bl[half * 2]), "r"(bl[half * 2 + 1]));
                        }
                    }
                }
            }
        }
        __syncthreads();
    }

    // epilogue: lo rows (m>=64, = Al@Bh) -> smem; hi rows add + store
    float* epi = (float*)(smc + SA);        // [64 m][128 n]
    if (wr >= 2) {
        #pragma unroll
        for (int mi = 0; mi < 2; mi++) {
            int r0 = (wr - 2) * 32 + mi * 16 + (lane >> 2);
            #pragma unroll
            for (int nf = 0; nf < 8; nf++) {
                int f = mi * 8 + nf;
                int col = wc * 64 + nf * 8 + (lane & 3) * 2;
                epi[r0 * 128 + col]           = d[f][0];
                epi[r0 * 128 + col + 1]       = d[f][1];
                epi[(r0 + 8) * 128 + col]     = d[f][2];
                epi[(r0 + 8) * 128 + col + 1] = d[f][3];
            }
        }
    }
    __syncthreads();
    if (wr < 2) {
        #pragma unroll
        for (int mi = 0; mi < 2; mi++) {
            int b0 = wr * 32 + mi * 16 + (lane >> 2);
            #pragma unroll
            for (int nf = 0; nf < 8; nf++) {
                int f = mi * 8 + nf;
                int col = wc * 64 + nf * 8 + (lane & 3) * 2;
                float2 r0v = make_float2(d[f][0] + epi[b0 * 128 + col],
                                         d[f][1] + epi[b0 * 128 + col + 1]);
                float2 r1v = make_float2(d[f][2] + epi[(b0 + 8) * 128 + col],
                                         d[f][3] + epi[(b0 + 8) * 128 + col + 1]);
                *(float2*)(out + ((size_t)b0 * STEPS + t) * VOCAB + v0 + col) = r0v;
                *(float2*)(out + ((size_t)(b0 + 8) * STEPS + t) * VOCAB + v0 + col) = r1v;
            }
        }
    }
}

// ---------------- launch ----------------
extern "C" void kernel_launch(void* const* d_in, const int* in_sizes, int n_in,
                              void* d_out, int out_size) {
    const float* V      = (const float*)d_in[0];
    const int*   y      = (const int*)  d_in[1];
    const float* embed  = (const float*)d_in[2];
    const float* W_att  = (const float*)d_in[3];
    const float* U_att  = (const float*)d_in[4];
    const float* v_att  = (const float*)d_in[5];
    const float* W_ih   = (const float*)d_in[6];
    const float* W_hh   = (const float*)d_in[7];
    const float* b_ih   = (const float*)d_in[8];
    const float* b_hh   = (const float*)d_in[9];
    const float* W_inith = (const float*)d_in[10];
    const float* b_inith = (const float*)d_in[11];
    const float* W_initc = (const float*)d_in[12];
    const float* b_initc = (const float*)d_in[13];
    const float* W_proj  = (const float*)d_in[14];
    float* out = (float*)d_out;

    const int SMEM_GATES = (256 * 68 + 256 * 64) * sizeof(float);  // 135168
    cudaFuncSetAttribute(k_gates, cudaFuncAttributeMaxDynamicSharedMemorySize, SMEM_GATES);
    cudaFuncSetAttribute(k_logits_mma, cudaFuncAttributeMaxDynamicSharedMemorySize, SM_LOG);

    k_init_hc<<<B, 512>>>(V, W_inith, b_inith, W_initc, b_initc);
    k_uv<<<(B * N) / UV_ROWS, 256>>>(V, U_att);
    k_esplit<<<(VOCAB * EMB) / 512, 256>>>(embed);
    k_hw0<<<B, 256>>>(W_att);                 // hW(h0) for step 0

    for (int t = 0; t < STEPS; t++) {
        k_att<<<B, 256>>>(v_att, V);
        k_gates<<<dim3(32, 4), 256, SMEM_GATES>>>(embed, y, W_ih, W_hh, t);
        k_lstm_proj<<<B, 512>>>(b_ih, b_hh, W_proj, W_att);
        k_logits_mma<<<VOCAB / 128, 256, SM_LOG>>>(out, t);
    }
}

// round 12
// speedup vs baseline: 1.5166x; 1.1582x over previous
#include <cuda_runtime.h>
#include <cuda_bf16.h>
#include <math.h>

#define B     64
#define N     196
#define TT    32
#define STEPS 31
#define VOCAB 32000
#define EMB   256
#define HDIM  512
#define VDIM  256
#define ATTD  256
#define G4    2048

// ---------------- scratch (device globals; no allocation) ----------------
__device__ float g_Uv[B * N * ATTD];
__device__ float g_h[B * HDIM];
__device__ float g_c[2][B * HDIM];        // parity double-buffer
__device__ float g_ctx[B * VDIM];
__device__ float g_hW[B * ATTD];
__device__ float g_gpart[4 * B * G4];     // split-K partials for gates
__device__ __align__(16) __nv_bfloat16 g_hpb[128 * EMB];        // rows 0-63 hi, 64-127 lo
__device__ __align__(16) __nv_bfloat16 g_eh[(size_t)VOCAB * EMB];
__device__ __align__(16) __nv_bfloat16 g_el[(size_t)VOCAB * EMB];

__device__ __forceinline__ float sigmoidf_(float x) { return 1.f / (1.f + expf(-x)); }
__device__ __forceinline__ float tanh_fast(float x) {
    float y;
    asm("tanh.approx.f32 %0, %1;" : "=f"(y) : "f"(x));
    return y;
}

// ---------------- packed f32x2 FMA helpers (SIMT GEMMs) ----------------
typedef unsigned long long ull;
struct Acc44 { ull a[4][2]; };
__device__ __forceinline__ ull fma2(ull a, ull b, ull c) {
    ull d; asm("fma.rn.f32x2 %0, %1, %2, %3;" : "=l"(d) : "l"(a), "l"(b), "l"(c));
    return d;
}
__device__ __forceinline__ ull pack2(float x) {
    ull d; unsigned int xi = __float_as_uint(x);
    asm("mov.b64 %0, {%1, %1};" : "=l"(d) : "r"(xi));
    return d;
}
__device__ __forceinline__ void acc_zero(Acc44& A) {
    #pragma unroll
    for (int i = 0; i < 4; i++) { A.a[i][0] = 0ull; A.a[i][1] = 0ull; }
}
__device__ __forceinline__ void mma44(Acc44& A, float4 xf, ulonglong2 wf) {
    ull h;
    h = pack2(xf.x); A.a[0][0] = fma2(h, wf.x, A.a[0][0]); A.a[0][1] = fma2(h, wf.y, A.a[0][1]);
    h = pack2(xf.y); A.a[1][0] = fma2(h, wf.x, A.a[1][0]); A.a[1][1] = fma2(h, wf.y, A.a[1][1]);
    h = pack2(xf.z); A.a[2][0] = fma2(h, wf.x, A.a[2][0]); A.a[2][1] = fma2(h, wf.y, A.a[2][1]);
    h = pack2(xf.w); A.a[3][0] = fma2(h, wf.x, A.a[3][0]); A.a[3][1] = fma2(h, wf.y, A.a[3][1]);
}
__device__ __forceinline__ float4 unpack44(const Acc44& A, int i) {
    unsigned int l0, h0, l1, h1;
    asm("mov.b64 {%0,%1}, %2;" : "=r"(l0), "=r"(h0) : "l"(A.a[i][0]));
    asm("mov.b64 {%0,%1}, %2;" : "=r"(l1), "=r"(h1) : "l"(A.a[i][1]));
    return make_float4(__uint_as_float(l0), __uint_as_float(h0),
                       __uint_as_float(l1), __uint_as_float(h1));
}

__device__ __forceinline__ unsigned smem_u32(const void* p) {
    unsigned a;
    asm("{ .reg .u64 t; cvta.to.shared.u64 t, %1; cvt.u32.u64 %0, t; }" : "=r"(a) : "l"(p));
    return a;
}

// ---------------- init: feat_mean -> h0, c0 ----------------
__global__ void k_init_hc(const float* __restrict__ V,
                          const float* __restrict__ Wh, const float* __restrict__ bh,
                          const float* __restrict__ Wc, const float* __restrict__ bc) {
    int b = blockIdx.x, tid = threadIdx.x;
    __shared__ float fm[VDIM];
    if (tid < VDIM) {
        const float* vp = V + (size_t)b * N * VDIM + tid;
        float s = 0.f;
        for (int n = 0; n < N; n++) s += vp[(size_t)n * VDIM];
        fm[tid] = s * (1.f / (float)N);
    }
    __syncthreads();
    int j = tid;
    float ah = bh[j], ac = bc[j];
    #pragma unroll 4
    for (int v = 0; v < VDIM; v++) {
        float f = fm[v];
        ah += f * Wh[(size_t)v * HDIM + j];
        ac += f * Wc[(size_t)v * HDIM + j];
    }
    g_h[b * HDIM + j] = tanhf(ah);
    g_c[0][b * HDIM + j] = tanhf(ac);
}

// ---------------- hW(h0) for step 0: 2 threads/j, 4 accumulators ----------------
// grid = B, block = 512
__global__ void k_hw0(const float* __restrict__ Watt) {
    int b = blockIdx.x, tid = threadIdx.x;
    __shared__ float hs[HDIM];
    __shared__ float red[512];
    hs[tid] = g_h[b * HDIM + tid];
    __syncthreads();
    int jl = tid & 255, kh = tid >> 8;
    const float* W = Watt + (size_t)(kh * 256) * ATTD + jl;
    const float* hp = hs + kh * 256;
    float a0 = 0.f, a1 = 0.f, a2 = 0.f, a3 = 0.f;
    #pragma unroll 8
    for (int k = 0; k < 256; k += 4) {
        a0 += hp[k]     * W[(size_t)k * ATTD];
        a1 += hp[k + 1] * W[(size_t)(k + 1) * ATTD];
        a2 += hp[k + 2] * W[(size_t)(k + 2) * ATTD];
        a3 += hp[k + 3] * W[(size_t)(k + 3) * ATTD];
    }
    red[tid] = (a0 + a1) + (a2 + a3);
    __syncthreads();
    if (kh == 0) g_hW[b * ATTD + jl] = red[jl] + red[jl + 256];
}

// ---------------- Uv = V @ U_att (once) ----------------
#define UV_ROWS 16
__global__ void k_uv(const float* __restrict__ V, const float* __restrict__ U) {
    __shared__ float Vs[UV_ROWS * VDIM];
    int r0 = blockIdx.x * UV_ROWS;
    int tid = threadIdx.x;
    for (int i = tid; i < UV_ROWS * VDIM; i += 256)
        Vs[i] = V[(size_t)r0 * VDIM + i];
    __syncthreads();
    float acc[UV_ROWS];
    #pragma unroll
    for (int i = 0; i < UV_ROWS; i++) acc[i] = 0.f;
    int a = tid;
    #pragma unroll 4
    for (int v = 0; v < VDIM; v++) {
        float u = U[(size_t)v * ATTD + a];
        #pragma unroll
        for (int i = 0; i < UV_ROWS; i++) acc[i] += Vs[i * VDIM + v] * u;
    }
    #pragma unroll
    for (int i = 0; i < UV_ROWS; i++)
        g_Uv[(size_t)(r0 + i) * ATTD + a] = acc[i];
}

// ---------------- embed -> bf16 hi/lo (once) ----------------
__global__ void k_esplit(const float* __restrict__ e) {
    size_t i = ((size_t)blockIdx.x * 256 + threadIdx.x) * 2;
    float2 v = *(const float2*)(e + i);
    __nv_bfloat16 h0 = __float2bfloat16(v.x);
    __nv_bfloat16 h1 = __float2bfloat16(v.y);
    __nv_bfloat16 l0 = __float2bfloat16(v.x - __bfloat162float(h0));
    __nv_bfloat16 l1 = __float2bfloat16(v.y - __bfloat162float(h1));
    *(__nv_bfloat162*)(g_eh + i) = __nv_bfloat162(h0, h1);
    *(__nv_bfloat162*)(g_el + i) = __nv_bfloat162(l0, l1);
}

// ---------------- fused attention: energies + softmax + ctx (512 threads) ----------------
// grid = B, block = 512
__global__ void k_att(const float* __restrict__ vatt, const float* __restrict__ V) {
    int b = blockIdx.x, tid = threadIdx.x;
    __shared__ float hWs[ATTD];
    __shared__ float vs[ATTD];
    __shared__ float es[256];
    __shared__ float red[256];
    __shared__ float ctxp[512];
    if (tid < 256) {
        hWs[tid] = g_hW[b * ATTD + tid];
        vs[tid] = vatt[tid];
    }
    __syncthreads();
    int warp = tid >> 5, lane = tid & 31;
    for (int n = warp; n < N; n += 16) {
        const float* uv = g_Uv + (size_t)(b * N + n) * ATTD;
        float p = 0.f;
        #pragma unroll
        for (int j = 0; j < 8; j++) {
            int a = lane + 32 * j;
            p += tanh_fast(hWs[a] + uv[a]) * vs[a];
        }
        #pragma unroll
        for (int off = 16; off > 0; off >>= 1)
            p += __shfl_down_sync(0xffffffffu, p, off);
        if (lane == 0) es[n] = p;
    }
    __syncthreads();
    float v = (tid < N) ? es[tid] : -INFINITY;
    if (tid < 256) red[tid] = v;
    __syncthreads();
    for (int s = 128; s > 0; s >>= 1) {
        if (tid < s) red[tid] = fmaxf(red[tid], red[tid + s]);
        __syncthreads();
    }
    float mx = red[0];
    __syncthreads();
    float ex = (tid < N) ? expf(v - mx) : 0.f;
    if (tid < 256) red[tid] = ex;
    __syncthreads();
    for (int s = 128; s > 0; s >>= 1) {
        if (tid < s) red[tid] += red[tid + s];
        __syncthreads();
    }
    float inv = 1.f / red[0];
    __syncthreads();
    if (tid < N) es[tid] = ex * inv;
    __syncthreads();
    // ctx: 2-way split over n
    int half = tid >> 8, vd = tid & 255;
    const float* vp = V + (size_t)b * N * VDIM + (size_t)half * 98 * VDIM + vd;
    float acc = 0.f;
    #pragma unroll 7
    for (int n = 0; n < 98; n++) acc += es[half * 98 + n] * vp[(size_t)n * VDIM];
    ctxp[tid] = acc;
    __syncthreads();
    if (tid < 256) g_ctx[b * VDIM + tid] = ctxp[tid] + ctxp[tid + 256];
}

// ---------------- gates GEMM: [64,1024] @ [1024,2048], split-K ----------------
__global__ void k_gates(const float* __restrict__ embed, const int* __restrict__ y,
                        const float* __restrict__ Wih, const float* __restrict__ Whh, int t) {
    extern __shared__ float sm[];
    float* Xs = sm;
    float* Ws = sm + 256 * 68;
    int j0 = blockIdx.x * 64;
    int kc = blockIdx.y;
    int tid = threadIdx.x;

    for (int idx = tid; idx < B * 256; idx += 256) {
        int kk = idx & 255, bb = idx >> 8;
        float x;
        if (kc == 0)      x = embed[(size_t)y[bb * TT + t] * EMB + kk];
        else if (kc == 1) x = g_ctx[bb * VDIM + kk];
        else if (kc == 2) x = g_h[bb * HDIM + kk];
        else              x = g_h[bb * HDIM + 256 + kk];
        Xs[kk * 68 + bb] = x;
    }
    const float* W = (kc < 2) ? (Wih + (size_t)(kc * 256) * G4)
                              : (Whh + (size_t)((kc - 2) * 256) * G4);
    for (int idx = tid; idx < 256 * 64; idx += 256) {
        int kk = idx >> 6, jj = idx & 63;
        Ws[idx] = W[(size_t)kk * G4 + j0 + jj];
    }
    __syncthreads();

    int tx = tid & 15, ty = tid >> 4;
    Acc44 A; acc_zero(A);
    #pragma unroll 4
    for (int kk = 0; kk < 256; kk++) {
        float4 xf = *(const float4*)&Xs[kk * 68 + ty * 4];
        ulonglong2 wf = *(const ulonglong2*)&Ws[kk * 64 + tx * 4];
        mma44(A, xf, wf);
    }
    float* gp = g_gpart + (size_t)kc * B * G4;
    #pragma unroll
    for (int i = 0; i < 4; i++) {
        int bb = ty * 4 + i;
        *(float4*)&gp[(size_t)bb * G4 + j0 + tx * 4] = unpack44(A, i);
    }
}

// ---------------- fused LSTM + proj, parallel: grid dim3(B,2), block 512 ----------------
// Both jc blocks redundantly compute LSTM h (c parity-buffered); jc=0 commits
// g_h/g_c and computes hp (bf16 hi/lo); jc=1 computes hW. 2 threads per output,
// 256 k each, 4 accumulators for MLP.
__global__ void k_lstm_proj2(const float* __restrict__ bih, const float* __restrict__ bhh,
                             const float* __restrict__ Wproj, const float* __restrict__ Watt,
                             int parity) {
    int b = blockIdx.x, jc = blockIdx.y, tid = threadIdx.x;
    __shared__ float hs[HDIM];
    __shared__ float red[512];

    // LSTM pointwise for j = tid (coalesced partial reads)
    int j = tid;
    float gi = bih[j]        + bhh[j];
    float gf = bih[512 + j]  + bhh[512 + j];
    float gg = bih[1024 + j] + bhh[1024 + j];
    float go = bih[1536 + j] + bhh[1536 + j];
    #pragma unroll
    for (int kc = 0; kc < 4; kc++) {
        const float* gp = g_gpart + (size_t)kc * B * G4 + (size_t)b * G4;
        gi += gp[j]; gf += gp[512 + j]; gg += gp[1024 + j]; go += gp[1536 + j];
    }
    float c = sigmoidf_(gf) * g_c[parity][b * HDIM + j] + sigmoidf_(gi) * tanhf(gg);
    float h = sigmoidf_(go) * tanhf(c);
    if (jc == 0) {
        g_c[parity ^ 1][b * HDIM + j] = c;
        g_h[b * HDIM + j] = h;
    }
    hs[j] = h;
    __syncthreads();

    // proj GEMV: output jg = jc*256 + jl; this thread covers k in [kh*256, +256)
    int jl = tid & 255, kh = tid >> 8;
    const float* W = ((jc == 0) ? Wproj : Watt) + (size_t)(kh * 256) * 256 + jl;
    const float* hp = hs + kh * 256;
    float a0 = 0.f, a1 = 0.f, a2 = 0.f, a3 = 0.f;
    #pragma unroll 8
    for (int k = 0; k < 256; k += 4) {
        a0 += hp[k]     * W[(size_t)k * 256];
        a1 += hp[k + 1] * W[(size_t)(k + 1) * 256];
        a2 += hp[k + 2] * W[(size_t)(k + 2) * 256];
        a3 += hp[k + 3] * W[(size_t)(k + 3) * 256];
    }
    red[tid] = (a0 + a1) + (a2 + a3);
    __syncthreads();
    if (kh == 0) {
        float s = red[jl] + red[jl + 256];
        if (jc == 0) {
            __nv_bfloat16 hi = __float2bfloat16(s);
            __nv_bfloat16 lo = __float2bfloat16(s - __bfloat162float(hi));
            g_hpb[b * EMB + jl] = hi;
            g_hpb[(64 + b) * EMB + jl] = lo;
        } else {
            g_hW[b * ATTD + jl] = s;
        }
    }
}

// ---------------- logits via mma.sync bf16 hi/lo split (ldmatrix B, AlBl skipped) ----------------
// grid = 250, block = 256 (8 warps: 4 m-rows x 2 n-cols), dyn smem = 102400
#define SA  0
#define SBH 32768
#define SBL (SBH + 34816)
#define SM_LOG (SBL + 34816)   // 102400

__global__ void __launch_bounds__(256, 2) k_logits_mma(float* __restrict__ out, int t) {
    extern __shared__ char smc[];
    const unsigned sb = smem_u32(smc);
    int tid = threadIdx.x;
    int wid = tid >> 5, lane = tid & 31;
    int wr = wid & 3, wc = wid >> 2;        // warp tile: rows wr*32.., cols wc*64..
    int v0 = blockIdx.x * 128;
    bool hiwarp = (wr < 2);                  // rows are hi(hp): needs Bh AND Bl

    float d[16][4];                          // f = mi*8 + ng
    #pragma unroll
    for (int f = 0; f < 16; f++) { d[f][0] = d[f][1] = d[f][2] = d[f][3] = 0.f; }

    // B ldmatrix lane->address components (fixed per thread)
    int bmat = lane >> 3, brow = lane & 7;
    int bn_local = ((bmat >> 1) << 3) + brow;   // 0..15 within a 16-n pair group
    unsigned bkoff = (unsigned)((bmat & 1) << 3) * 2;  // 0 or 16 bytes

    #pragma unroll
    for (int kc = 0; kc < 2; kc++) {
        // A chunk: g_hpb[m][kc*128..+127] -> swizzled smem
        for (int i = tid; i < 2048; i += 256) {
            int m = i >> 4, u = i & 15;
            *(uint4*)(smc + SA + m * 256 + ((u ^ (m & 7)) << 4)) =
                *(const uint4*)((const char*)g_hpb + (size_t)m * 512 + kc * 256 + u * 16);
        }
        // B chunks (hi & lo), rows padded to 272B
        for (int i = tid; i < 2048; i += 256) {
            int n = i >> 4, u = i & 15;
            size_t go = (size_t)(v0 + n) * 512 + kc * 256 + u * 16;
            *(uint4*)(smc + SBH + n * 272 + u * 16) = *(const uint4*)((const char*)g_eh + go);
            *(uint4*)(smc + SBL + n * 272 + u * 16) = *(const uint4*)((const char*)g_el + go);
        }
        __syncthreads();

        #pragma unroll
        for (int ks = 0; ks < 8; ks++) {
            // A fragments (2 per warp) via ldmatrix.x4
            unsigned a[2][4];
            #pragma unroll
            for (int mi = 0; mi < 2; mi++) {
                int m = wr * 32 + mi * 16 + ((lane >> 3) & 1) * 8 + (lane & 7);
                int u = ks * 2 + (lane >> 4);
                unsigned addr = sb + SA + m * 256 + ((u ^ (m & 7)) << 4);
                asm volatile(
                    "ldmatrix.sync.aligned.m8n8.x4.shared.b16 {%0,%1,%2,%3}, [%4];"
                    : "=r"(a[mi][0]), "=r"(a[mi][1]), "=r"(a[mi][2]), "=r"(a[mi][3])
                    : "r"(addr));
            }
            unsigned bko = (unsigned)(ks * 32) + bkoff;   // ks*16 k-elems * 2B + half
            #pragma unroll
            for (int np = 0; np < 4; np++) {              // 4 pairs of n8 groups
                unsigned brow_addr = sb + SBH +
                    (unsigned)((wc * 64 + np * 16 + bn_local) * 272) + bko;
                unsigned bh[4];
                asm volatile(
                    "ldmatrix.sync.aligned.m8n8.x4.shared.b16 {%0,%1,%2,%3}, [%4];"
                    : "=r"(bh[0]), "=r"(bh[1]), "=r"(bh[2]), "=r"(bh[3])
                    : "r"(brow_addr));
                #pragma unroll
                for (int half = 0; half < 2; half++) {
                    int f0 = np * 2 + half;
                    #pragma unroll
                    for (int mi = 0; mi < 2; mi++) {
                        int f = mi * 8 + f0;
                        asm volatile(
                            "mma.sync.aligned.m16n8k16.row.col.f32.bf16.bf16.f32 "
                            "{%0,%1,%2,%3}, {%4,%5,%6,%7}, {%8,%9}, {%0,%1,%2,%3};"
                            : "+f"(d[f][0]), "+f"(d[f][1]), "+f"(d[f][2]), "+f"(d[f][3])
                            : "r"(a[mi][0]), "r"(a[mi][1]), "r"(a[mi][2]), "r"(a[mi][3]),
                              "r"(bh[half * 2]), "r"(bh[half * 2 + 1]));
                    }
                }
                if (hiwarp) {
                    unsigned blo_addr = brow_addr + (SBL - SBH);
                    unsigned bl[4];
                    asm volatile(
                        "ldmatrix.sync.aligned.m8n8.x4.shared.b16 {%0,%1,%2,%3}, [%4];"
                        : "=r"(bl[0]), "=r"(bl[1]), "=r"(bl[2]), "=r"(bl[3])
                        : "r"(blo_addr));
                    #pragma unroll
                    for (int half = 0; half < 2; half++) {
                        int f0 = np * 2 + half;
                        #pragma unroll
                        for (int mi = 0; mi < 2; mi++) {
                            int f = mi * 8 + f0;
                            asm volatile(
                                "mma.sync.aligned.m16n8k16.row.col.f32.bf16.bf16.f32 "
                                "{%0,%1,%2,%3}, {%4,%5,%6,%7}, {%8,%9}, {%0,%1,%2,%3};"
                                : "+f"(d[f][0]), "+f"(d[f][1]), "+f"(d[f][2]), "+f"(d[f][3])
                                : "r"(a[mi][0]), "r"(a[mi][1]), "r"(a[mi][2]), "r"(a[mi][3]),
                                  "r"(bl[half * 2]), "r"(bl[half * 2 + 1]));
                        }
                    }
                }
            }
        }
        __syncthreads();
    }

    // epilogue: lo rows (m>=64, = Al@Bh) -> smem; hi rows add + store
    float* epi = (float*)(smc + SA);        // [64 m][128 n]
    if (wr >= 2) {
        #pragma unroll
        for (int mi = 0; mi < 2; mi++) {
            int r0 = (wr - 2) * 32 + mi * 16 + (lane >> 2);
            #pragma unroll
            for (int nf = 0; nf < 8; nf++) {
                int f = mi * 8 + nf;
                int col = wc * 64 + nf * 8 + (lane & 3) * 2;
                epi[r0 * 128 + col]           = d[f][0];
                epi[r0 * 128 + col + 1]       = d[f][1];
                epi[(r0 + 8) * 128 + col]     = d[f][2];
                epi[(r0 + 8) * 128 + col + 1] = d[f][3];
            }
        }
    }
    __syncthreads();
    if (wr < 2) {
        #pragma unroll
        for (int mi = 0; mi < 2; mi++) {
            int b0 = wr * 32 + mi * 16 + (lane >> 2);
            #pragma unroll
            for (int nf = 0; nf < 8; nf++) {
                int f = mi * 8 + nf;
                int col = wc * 64 + nf * 8 + (lane & 3) * 2;
                float2 r0v = make_float2(d[f][0] + epi[b0 * 128 + col],
                                         d[f][1] + epi[b0 * 128 + col + 1]);
                float2 r1v = make_float2(d[f][2] + epi[(b0 + 8) * 128 + col],
                                         d[f][3] + epi[(b0 + 8) * 128 + col + 1]);
                *(float2*)(out + ((size_t)b0 * STEPS + t) * VOCAB + v0 + col) = r0v;
                *(float2*)(out + ((size_t)(b0 + 8) * STEPS + t) * VOCAB + v0 + col) = r1v;
            }
        }
    }
}

// ---------------- launch ----------------
extern "C" void kernel_launch(void* const* d_in, const int* in_sizes, int n_in,
                              void* d_out, int out_size) {
    const float* V      = (const float*)d_in[0];
    const int*   y      = (const int*)  d_in[1];
    const float* embed  = (const float*)d_in[2];
    const float* W_att  = (const float*)d_in[3];
    const float* U_att  = (const float*)d_in[4];
    const float* v_att  = (const float*)d_in[5];
    const float* W_ih   = (const float*)d_in[6];
    const float* W_hh   = (const float*)d_in[7];
    const float* b_ih   = (const float*)d_in[8];
    const float* b_hh   = (const float*)d_in[9];
    const float* W_inith = (const float*)d_in[10];
    const float* b_inith = (const float*)d_in[11];
    const float* W_initc = (const float*)d_in[12];
    const float* b_initc = (const float*)d_in[13];
    const float* W_proj  = (const float*)d_in[14];
    float* out = (float*)d_out;

    const int SMEM_GATES = (256 * 68 + 256 * 64) * sizeof(float);  // 135168
    cudaFuncSetAttribute(k_gates, cudaFuncAttributeMaxDynamicSharedMemorySize, SMEM_GATES);
    cudaFuncSetAttribute(k_logits_mma, cudaFuncAttributeMaxDynamicSharedMemorySize, SM_LOG);

    k_init_hc<<<B, 512>>>(V, W_inith, b_inith, W_initc, b_initc);
    k_uv<<<(B * N) / UV_ROWS, 256>>>(V, U_att);
    k_esplit<<<(VOCAB * EMB) / 512, 256>>>(embed);
    k_hw0<<<B, 512>>>(W_att);                 // hW(h0) for step 0

    for (int t = 0; t < STEPS; t++) {
        k_att<<<B, 512>>>(v_att, V);
        k_gates<<<dim3(32, 4), 256, SMEM_GATES>>>(embed, y, W_ih, W_hh, t);
        k_lstm_proj2<<<dim3(B, 2), 512>>>(b_ih, b_hh, W_proj, W_att, t & 1);
        k_logits_mma<<<VOCAB / 128, 256, SM_LOG>>>(out, t);
    }
}

// round 13
// speedup vs baseline: 2.1965x; 1.4484x over previous
#include <cuda_runtime.h>
#include <cuda_bf16.h>
#include <math.h>

#define B     64
#define N     196
#define TT    32
#define STEPS 31
#define VOCAB 32000
#define EMB   256
#define HDIM  512
#define VDIM  256
#define ATTD  256
#define G4    2048

// ---------------- scratch (device globals; no allocation) ----------------
__device__ float g_Uv[B * N * ATTD];
__device__ float g_h[B * HDIM];
__device__ float g_c[2][B * HDIM];        // parity double-buffer
__device__ float g_ctx[B * VDIM];
__device__ float g_hW[B * ATTD];          // prologue only
__device__ float g_gpart[8 * B * G4];     // split-K partials for gates (8 chunks)
__device__ __align__(16) __nv_bfloat16 g_hpb[128 * EMB];        // rows 0-63 hi, 64-127 lo
__device__ __align__(16) __nv_bfloat16 g_eh[(size_t)VOCAB * EMB];
__device__ __align__(16) __nv_bfloat16 g_el[(size_t)VOCAB * EMB];

__device__ __forceinline__ float sigmoidf_(float x) { return 1.f / (1.f + expf(-x)); }
__device__ __forceinline__ float tanh_fast(float x) {
    float y;
    asm("tanh.approx.f32 %0, %1;" : "=f"(y) : "f"(x));
    return y;
}

// ---------------- packed f32x2 FMA helpers (SIMT GEMMs) ----------------
typedef unsigned long long ull;
struct Acc44 { ull a[4][2]; };
__device__ __forceinline__ ull fma2(ull a, ull b, ull c) {
    ull d; asm("fma.rn.f32x2 %0, %1, %2, %3;" : "=l"(d) : "l"(a), "l"(b), "l"(c));
    return d;
}
__device__ __forceinline__ ull pack2(float x) {
    ull d; unsigned int xi = __float_as_uint(x);
    asm("mov.b64 %0, {%1, %1};" : "=l"(d) : "r"(xi));
    return d;
}
__device__ __forceinline__ void acc_zero(Acc44& A) {
    #pragma unroll
    for (int i = 0; i < 4; i++) { A.a[i][0] = 0ull; A.a[i][1] = 0ull; }
}
__device__ __forceinline__ void mma44(Acc44& A, float4 xf, ulonglong2 wf) {
    ull h;
    h = pack2(xf.x); A.a[0][0] = fma2(h, wf.x, A.a[0][0]); A.a[0][1] = fma2(h, wf.y, A.a[0][1]);
    h = pack2(xf.y); A.a[1][0] = fma2(h, wf.x, A.a[1][0]); A.a[1][1] = fma2(h, wf.y, A.a[1][1]);
    h = pack2(xf.z); A.a[2][0] = fma2(h, wf.x, A.a[2][0]); A.a[2][1] = fma2(h, wf.y, A.a[2][1]);
    h = pack2(xf.w); A.a[3][0] = fma2(h, wf.x, A.a[3][0]); A.a[3][1] = fma2(h, wf.y, A.a[3][1]);
}
__device__ __forceinline__ float4 unpack44(const Acc44& A, int i) {
    unsigned int l0, h0, l1, h1;
    asm("mov.b64 {%0,%1}, %2;" : "=r"(l0), "=r"(h0) : "l"(A.a[i][0]));
    asm("mov.b64 {%0,%1}, %2;" : "=r"(l1), "=r"(h1) : "l"(A.a[i][1]));
    return make_float4(__uint_as_float(l0), __uint_as_float(h0),
                       __uint_as_float(l1), __uint_as_float(h1));
}

__device__ __forceinline__ unsigned smem_u32(const void* p) {
    unsigned a;
    asm("{ .reg .u64 t; cvta.to.shared.u64 t, %1; cvt.u32.u64 %0, t; }" : "=r"(a) : "l"(p));
    return a;
}

// ---------------- init: feat_mean -> h0, c0 ----------------
__global__ void k_init_hc(const float* __restrict__ V,
                          const float* __restrict__ Wh, const float* __restrict__ bh,
                          const float* __restrict__ Wc, const float* __restrict__ bc) {
    int b = blockIdx.x, tid = threadIdx.x;
    __shared__ float fm[VDIM];
    if (tid < VDIM) {
        const float* vp = V + (size_t)b * N * VDIM + tid;
        float s = 0.f;
        for (int n = 0; n < N; n++) s += vp[(size_t)n * VDIM];
        fm[tid] = s * (1.f / (float)N);
    }
    __syncthreads();
    int j = tid;
    float ah = bh[j], ac = bc[j];
    #pragma unroll 4
    for (int v = 0; v < VDIM; v++) {
        float f = fm[v];
        ah += f * Wh[(size_t)v * HDIM + j];
        ac += f * Wc[(size_t)v * HDIM + j];
    }
    g_h[b * HDIM + j] = tanhf(ah);
    g_c[0][b * HDIM + j] = tanhf(ac);
}

// ---------------- hW(h0) for step 0: 4 threads/j ----------------
// grid = B, block = 1024
__global__ void k_hw0(const float* __restrict__ Watt) {
    int b = blockIdx.x, tid = threadIdx.x;
    __shared__ float hs[HDIM];
    __shared__ float red[1024];
    if (tid < 512) hs[tid] = g_h[b * HDIM + tid];
    __syncthreads();
    int jl = tid & 255, kh = tid >> 8;
    const float* W = Watt + (size_t)(kh * 128) * ATTD + jl;
    const float* hp = hs + kh * 128;
    float a0 = 0.f, a1 = 0.f, a2 = 0.f, a3 = 0.f;
    #pragma unroll 8
    for (int k = 0; k < 128; k += 4) {
        a0 += hp[k]     * W[(size_t)k * ATTD];
        a1 += hp[k + 1] * W[(size_t)(k + 1) * ATTD];
        a2 += hp[k + 2] * W[(size_t)(k + 2) * ATTD];
        a3 += hp[k + 3] * W[(size_t)(k + 3) * ATTD];
    }
    red[tid] = (a0 + a1) + (a2 + a3);
    __syncthreads();
    if (tid < 256)
        g_hW[b * ATTD + jl] = (red[jl] + red[jl + 256]) + (red[jl + 512] + red[jl + 768]);
}

// ---------------- Uv = V @ U_att (once) ----------------
#define UV_ROWS 16
__global__ void k_uv(const float* __restrict__ V, const float* __restrict__ U) {
    __shared__ float Vs[UV_ROWS * VDIM];
    int r0 = blockIdx.x * UV_ROWS;
    int tid = threadIdx.x;
    for (int i = tid; i < UV_ROWS * VDIM; i += 256)
        Vs[i] = V[(size_t)r0 * VDIM + i];
    __syncthreads();
    float acc[UV_ROWS];
    #pragma unroll
    for (int i = 0; i < UV_ROWS; i++) acc[i] = 0.f;
    int a = tid;
    #pragma unroll 4
    for (int v = 0; v < VDIM; v++) {
        float u = U[(size_t)v * ATTD + a];
        #pragma unroll
        for (int i = 0; i < UV_ROWS; i++) acc[i] += Vs[i * VDIM + v] * u;
    }
    #pragma unroll
    for (int i = 0; i < UV_ROWS; i++)
        g_Uv[(size_t)(r0 + i) * ATTD + a] = acc[i];
}

// ---------------- embed -> bf16 hi/lo (once) ----------------
__global__ void k_esplit(const float* __restrict__ e) {
    size_t i = ((size_t)blockIdx.x * 256 + threadIdx.x) * 2;
    float2 v = *(const float2*)(e + i);
    __nv_bfloat16 h0 = __float2bfloat16(v.x);
    __nv_bfloat16 h1 = __float2bfloat16(v.y);
    __nv_bfloat16 l0 = __float2bfloat16(v.x - __bfloat162float(h0));
    __nv_bfloat16 l1 = __float2bfloat16(v.y - __bfloat162float(h1));
    *(__nv_bfloat162*)(g_eh + i) = __nv_bfloat162(h0, h1);
    *(__nv_bfloat162*)(g_el + i) = __nv_bfloat162(l0, l1);
}

// ---------------- prologue attention (ctx for step 0, reads g_hW) ----------------
// grid = B, block = 512
__global__ void k_att0(const float* __restrict__ vatt, const float* __restrict__ V) {
    int b = blockIdx.x, tid = threadIdx.x;
    __shared__ float hWs[ATTD];
    __shared__ float vs[ATTD];
    __shared__ float es[256];
    __shared__ float red[256];
    __shared__ float ctxp[512];
    if (tid < 256) {
        hWs[tid] = g_hW[b * ATTD + tid];
        vs[tid] = vatt[tid];
    }
    __syncthreads();
    int warp = tid >> 5, lane = tid & 31;
    for (int n = warp; n < N; n += 16) {
        const float* uv = g_Uv + (size_t)(b * N + n) * ATTD;
        float p = 0.f;
        #pragma unroll
        for (int j = 0; j < 8; j++) {
            int a = lane + 32 * j;
            p += tanh_fast(hWs[a] + uv[a]) * vs[a];
        }
        #pragma unroll
        for (int off = 16; off > 0; off >>= 1)
            p += __shfl_down_sync(0xffffffffu, p, off);
        if (lane == 0) es[n] = p;
    }
    __syncthreads();
    float v = (tid < N) ? es[tid] : -INFINITY;
    if (tid < 256) red[tid] = v;
    __syncthreads();
    for (int s = 128; s > 0; s >>= 1) {
        if (tid < s) red[tid] = fmaxf(red[tid], red[tid + s]);
        __syncthreads();
    }
    float mx = red[0];
    __syncthreads();
    float ex = (tid < N) ? expf(v - mx) : 0.f;
    if (tid < 256) red[tid] = ex;
    __syncthreads();
    for (int s = 128; s > 0; s >>= 1) {
        if (tid < s) red[tid] += red[tid + s];
        __syncthreads();
    }
    float inv = 1.f / red[0];
    __syncthreads();
    if (tid < N) es[tid] = ex * inv;
    __syncthreads();
    int half = tid >> 8, vd = tid & 255;
    const float* vp = V + (size_t)b * N * VDIM + (size_t)half * 98 * VDIM + vd;
    float acc = 0.f;
    #pragma unroll 7
    for (int n = 0; n < 98; n++) acc += es[half * 98 + n] * vp[(size_t)n * VDIM];
    ctxp[tid] = acc;
    __syncthreads();
    if (tid < 256) g_ctx[b * VDIM + tid] = ctxp[tid] + ctxp[tid + 256];
}

// ---------------- gates GEMM: [64,1024] @ [1024,2048], split-K x8 ----------------
// grid = dim3(32, 8), block = 256, dyn smem = 67584
__global__ void k_gates(const float* __restrict__ embed, const int* __restrict__ y,
                        const float* __restrict__ Wih, const float* __restrict__ Whh, int t) {
    extern __shared__ float sm[];
    float* Xs = sm;                // [128 kk][68 pad]
    float* Ws = sm + 128 * 68;     // [128 kk][64 jj]
    int j0 = blockIdx.x * 64;
    int kc = blockIdx.y;
    int tid = threadIdx.x;

    for (int idx = tid; idx < B * 128; idx += 256) {
        int kk = idx & 127, bb = idx >> 7;
        int gk = kc * 128 + kk;
        float x;
        if (gk < 256)      x = embed[(size_t)y[bb * TT + t] * EMB + gk];
        else if (gk < 512) x = g_ctx[bb * VDIM + (gk - 256)];
        else               x = g_h[bb * HDIM + (gk - 512)];
        Xs[kk * 68 + bb] = x;
    }
    const float* W = (kc < 4) ? (Wih + (size_t)(kc * 128) * G4)
                              : (Whh + (size_t)((kc - 4) * 128) * G4);
    for (int idx = tid; idx < 128 * 64; idx += 256) {
        int kk = idx >> 6, jj = idx & 63;
        Ws[idx] = W[(size_t)kk * G4 + j0 + jj];
    }
    __syncthreads();

    int tx = tid & 15, ty = tid >> 4;
    Acc44 A; acc_zero(A);
    #pragma unroll 4
    for (int kk = 0; kk < 128; kk++) {
        float4 xf = *(const float4*)&Xs[kk * 68 + ty * 4];
        ulonglong2 wf = *(const ulonglong2*)&Ws[kk * 64 + tx * 4];
        mma44(A, xf, wf);
    }
    float* gp = g_gpart + (size_t)kc * B * G4;
    #pragma unroll
    for (int i = 0; i < 4; i++) {
        int bb = ty * 4 + i;
        *(float4*)&gp[(size_t)bb * G4 + j0 + tx * 4] = unpack44(A, i);
    }
}

// ---------------- fused LSTM + proj GEMV + attention(t+1) ----------------
// grid = dim3(B, 2), block = 1024.
// Both jc blocks compute LSTM h (jc=0 commits g_h/g_c). GEMV: 4 threads/output.
// jc=0 -> hp (bf16 hi/lo). jc=1 -> hW (kept in smem) then full attention:
// energies + softmax + ctx for batch b -> g_ctx (consumed by next step's gates).
__global__ void k_lstm_fused(const float* __restrict__ bih, const float* __restrict__ bhh,
                             const float* __restrict__ Wproj, const float* __restrict__ Watt,
                             const float* __restrict__ vatt, const float* __restrict__ V,
                             int parity) {
    int b = blockIdx.x, jc = blockIdx.y, tid = threadIdx.x;
    __shared__ float hs[HDIM];
    __shared__ float red[1024];
    __shared__ float hWs[ATTD];
    __shared__ float vs[ATTD];
    __shared__ float es[256];
    __shared__ float sred[256];

    // LSTM pointwise (threads 0..511), coalesced partial reads over 8 chunks
    if (tid < 512) {
        int j = tid;
        float gi = bih[j]        + bhh[j];
        float gf = bih[512 + j]  + bhh[512 + j];
        float gg = bih[1024 + j] + bhh[1024 + j];
        float go = bih[1536 + j] + bhh[1536 + j];
        #pragma unroll
        for (int kc = 0; kc < 8; kc++) {
            const float* gp = g_gpart + (size_t)kc * B * G4 + (size_t)b * G4;
            gi += gp[j]; gf += gp[512 + j]; gg += gp[1024 + j]; go += gp[1536 + j];
        }
        float c = sigmoidf_(gf) * g_c[parity][b * HDIM + j] + sigmoidf_(gi) * tanhf(gg);
        float h = sigmoidf_(go) * tanhf(c);
        if (jc == 0) {
            g_c[parity ^ 1][b * HDIM + j] = c;
            g_h[b * HDIM + j] = h;
        }
        hs[j] = h;
    }
    __syncthreads();

    // GEMV: output jl (0..255), 4 threads each over 128 k
    int jl = tid & 255, kh = tid >> 8;
    const float* W = ((jc == 0) ? Wproj : Watt) + (size_t)(kh * 128) * 256 + jl;
    const float* hp = hs + kh * 128;
    float a0 = 0.f, a1 = 0.f, a2 = 0.f, a3 = 0.f;
    #pragma unroll 8
    for (int k = 0; k < 128; k += 4) {
        a0 += hp[k]     * W[(size_t)k * 256];
        a1 += hp[k + 1] * W[(size_t)(k + 1) * 256];
        a2 += hp[k + 2] * W[(size_t)(k + 2) * 256];
        a3 += hp[k + 3] * W[(size_t)(k + 3) * 256];
    }
    red[tid] = (a0 + a1) + (a2 + a3);
    __syncthreads();
    if (tid < 256) {
        float s = (red[jl] + red[jl + 256]) + (red[jl + 512] + red[jl + 768]);
        if (jc == 0) {
            __nv_bfloat16 hi = __float2bfloat16(s);
            __nv_bfloat16 lo = __float2bfloat16(s - __bfloat162float(hi));
            g_hpb[b * EMB + jl] = hi;
            g_hpb[(64 + b) * EMB + jl] = lo;
        } else {
            hWs[jl] = s;
            vs[jl] = vatt[jl];
        }
    }
    if (jc == 0) return;

    // ---- attention for next step (jc == 1 block only) ----
    __syncthreads();
    int warp = tid >> 5, lane = tid & 31;
    for (int n = warp; n < N; n += 32) {
        const float* uv = g_Uv + (size_t)(b * N + n) * ATTD;
        float p = 0.f;
        #pragma unroll
        for (int j = 0; j < 8; j++) {
            int a = lane + 32 * j;
            p += tanh_fast(hWs[a] + uv[a]) * vs[a];
        }
        #pragma unroll
        for (int off = 16; off > 0; off >>= 1)
            p += __shfl_down_sync(0xffffffffu, p, off);
        if (lane == 0) es[n] = p;
    }
    __syncthreads();
    float v = (tid < N) ? es[tid] : -INFINITY;
    if (tid < 256) sred[tid] = v;
    __syncthreads();
    for (int s = 128; s > 0; s >>= 1) {
        if (tid < s) sred[tid] = fmaxf(sred[tid], sred[tid + s]);
        __syncthreads();
    }
    float mx = sred[0];
    __syncthreads();
    float ex = (tid < N) ? expf(v - mx) : 0.f;
    if (tid < 256) sred[tid] = ex;
    __syncthreads();
    for (int s = 128; s > 0; s >>= 1) {
        if (tid < s) sred[tid] += sred[tid + s];
        __syncthreads();
    }
    float inv = 1.f / sred[0];
    __syncthreads();
    if (tid < N) es[tid] = ex * inv;
    __syncthreads();
    // ctx: 4-way split over n (49 each), reduce via red[]
    int q = tid >> 8, vd = tid & 255;
    const float* vp = V + (size_t)b * N * VDIM + (size_t)q * 49 * VDIM + vd;
    float acc = 0.f;
    #pragma unroll 7
    for (int n = 0; n < 49; n++) acc += es[q * 49 + n] * vp[(size_t)n * VDIM];
    red[tid] = acc;
    __syncthreads();
    if (tid < 256)
        g_ctx[b * VDIM + vd] = (red[vd] + red[vd + 256]) + (red[vd + 512] + red[vd + 768]);
}

// ---------------- logits via mma.sync bf16 hi/lo split (ldmatrix B, AlBl skipped) ----------------
// grid = 250, block = 256 (8 warps: 4 m-rows x 2 n-cols), dyn smem = 102400
#define SA  0
#define SBH 32768
#define SBL (SBH + 34816)
#define SM_LOG (SBL + 34816)   // 102400

__global__ void __launch_bounds__(256, 2) k_logits_mma(float* __restrict__ out, int t) {
    extern __shared__ char smc[];
    const unsigned sb = smem_u32(smc);
    int tid = threadIdx.x;
    int wid = tid >> 5, lane = tid & 31;
    int wr = wid & 3, wc = wid >> 2;        // warp tile: rows wr*32.., cols wc*64..
    int v0 = blockIdx.x * 128;
    bool hiwarp = (wr < 2);                  // rows are hi(hp): needs Bh AND Bl

    float d[16][4];
    #pragma unroll
    for (int f = 0; f < 16; f++) { d[f][0] = d[f][1] = d[f][2] = d[f][3] = 0.f; }

    int bmat = lane >> 3, brow = lane & 7;
    int bn_local = ((bmat >> 1) << 3) + brow;
    unsigned bkoff = (unsigned)((bmat & 1) << 3) * 2;

    #pragma unroll
    for (int kc = 0; kc < 2; kc++) {
        for (int i = tid; i < 2048; i += 256) {
            int m = i >> 4, u = i & 15;
            *(uint4*)(smc + SA + m * 256 + ((u ^ (m & 7)) << 4)) =
                *(const uint4*)((const char*)g_hpb + (size_t)m * 512 + kc * 256 + u * 16);
        }
        for (int i = tid; i < 2048; i += 256) {
            int n = i >> 4, u = i & 15;
            size_t go = (size_t)(v0 + n) * 512 + kc * 256 + u * 16;
            *(uint4*)(smc + SBH + n * 272 + u * 16) = *(const uint4*)((const char*)g_eh + go);
            *(uint4*)(smc + SBL + n * 272 + u * 16) = *(const uint4*)((const char*)g_el + go);
        }
        __syncthreads();

        #pragma unroll
        for (int ks = 0; ks < 8; ks++) {
            unsigned a[2][4];
            #pragma unroll
            for (int mi = 0; mi < 2; mi++) {
                int m = wr * 32 + mi * 16 + ((lane >> 3) & 1) * 8 + (lane & 7);
                int u = ks * 2 + (lane >> 4);
                unsigned addr = sb + SA + m * 256 + ((u ^ (m & 7)) << 4);
                asm volatile(
                    "ldmatrix.sync.aligned.m8n8.x4.shared.b16 {%0,%1,%2,%3}, [%4];"
                    : "=r"(a[mi][0]), "=r"(a[mi][1]), "=r"(a[mi][2]), "=r"(a[mi][3])
                    : "r"(addr));
            }
            unsigned bko = (unsigned)(ks * 32) + bkoff;
            #pragma unroll
            for (int np = 0; np < 4; np++) {
                unsigned brow_addr = sb + SBH +
                    (unsigned)((wc * 64 + np * 16 + bn_local) * 272) + bko;
                unsigned bh[4];
                asm volatile(
                    "ldmatrix.sync.aligned.m8n8.x4.shared.b16 {%0,%1,%2,%3}, [%4];"
                    : "=r"(bh[0]), "=r"(bh[1]), "=r"(bh[2]), "=r"(bh[3])
                    : "r"(brow_addr));
                #pragma unroll
                for (int half = 0; half < 2; half++) {
                    int f0 = np * 2 + half;
                    #pragma unroll
                    for (int mi = 0; mi < 2; mi++) {
                        int f = mi * 8 + f0;
                        asm volatile(
                            "mma.sync.aligned.m16n8k16.row.col.f32.bf16.bf16.f32 "
                            "{%0,%1,%2,%3}, {%4,%5,%6,%7}, {%8,%9}, {%0,%1,%2,%3};"
                            : "+f"(d[f][0]), "+f"(d[f][1]), "+f"(d[f][2]), "+f"(d[f][3])
                            : "r"(a[mi][0]), "r"(a[mi][1]), "r"(a[mi][2]), "r"(a[mi][3]),
                              "r"(bh[half * 2]), "r"(bh[half * 2 + 1]));
                    }
                }
                if (hiwarp) {
                    unsigned blo_addr = brow_addr + (SBL - SBH);
                    unsigned bl[4];
                    asm volatile(
                        "ldmatrix.sync.aligned.m8n8.x4.shared.b16 {%0,%1,%2,%3}, [%4];"
                        : "=r"(bl[0]), "=r"(bl[1]), "=r"(bl[2]), "=r"(bl[3])
                        : "r"(blo_addr));
                    #pragma unroll
                    for (int half = 0; half < 2; half++) {
                        int f0 = np * 2 + half;
                        #pragma unroll
                        for (int mi = 0; mi < 2; mi++) {
                            int f = mi * 8 + f0;
                            asm volatile(
                                "mma.sync.aligned.m16n8k16.row.col.f32.bf16.bf16.f32 "
                                "{%0,%1,%2,%3}, {%4,%5,%6,%7}, {%8,%9}, {%0,%1,%2,%3};"
                                : "+f"(d[f][0]), "+f"(d[f][1]), "+f"(d[f][2]), "+f"(d[f][3])
                                : "r"(a[mi][0]), "r"(a[mi][1]), "r"(a[mi][2]), "r"(a[mi][3]),
                                  "r"(bl[half * 2]), "r"(bl[half * 2 + 1]));
                        }
                    }
                }
            }
        }
        __syncthreads();
    }

    float* epi = (float*)(smc + SA);
    if (wr >= 2) {
        #pragma unroll
        for (int mi = 0; mi < 2; mi++) {
            int r0 = (wr - 2) * 32 + mi * 16 + (lane >> 2);
            #pragma unroll
            for (int nf = 0; nf < 8; nf++) {
                int f = mi * 8 + nf;
                int col = wc * 64 + nf * 8 + (lane & 3) * 2;
                epi[r0 * 128 + col]           = d[f][0];
                epi[r0 * 128 + col + 1]       = d[f][1];
                epi[(r0 + 8) * 128 + col]     = d[f][2];
                epi[(r0 + 8) * 128 + col + 1] = d[f][3];
            }
        }
    }
    __syncthreads();
    if (wr < 2) {
        #pragma unroll
        for (int mi = 0; mi < 2; mi++) {
            int b0 = wr * 32 + mi * 16 + (lane >> 2);
            #pragma unroll
            for (int nf = 0; nf < 8; nf++) {
                int f = mi * 8 + nf;
                int col = wc * 64 + nf * 8 + (lane & 3) * 2;
                float2 r0v = make_float2(d[f][0] + epi[b0 * 128 + col],
                                         d[f][1] + epi[b0 * 128 + col + 1]);
                float2 r1v = make_float2(d[f][2] + epi[(b0 + 8) * 128 + col],
                                         d[f][3] + epi[(b0 + 8) * 128 + col + 1]);
                *(float2*)(out + ((size_t)b0 * STEPS + t) * VOCAB + v0 + col) = r0v;
                *(float2*)(out + ((size_t)(b0 + 8) * STEPS + t) * VOCAB + v0 + col) = r1v;
            }
        }
    }
}

// ---------------- launch ----------------
extern "C" void kernel_launch(void* const* d_in, const int* in_sizes, int n_in,
                              void* d_out, int out_size) {
    const float* V      = (const float*)d_in[0];
    const int*   y      = (const int*)  d_in[1];
    const float* embed  = (const float*)d_in[2];
    const float* W_att  = (const float*)d_in[3];
    const float* U_att  = (const float*)d_in[4];
    const float* v_att  = (const float*)d_in[5];
    const float* W_ih   = (const float*)d_in[6];
    const float* W_hh   = (const float*)d_in[7];
    const float* b_ih   = (const float*)d_in[8];
    const float* b_hh   = (const float*)d_in[9];
    const float* W_inith = (const float*)d_in[10];
    const float* b_inith = (const float*)d_in[11];
    const float* W_initc = (const float*)d_in[12];
    const float* b_initc = (const float*)d_in[13];
    const float* W_proj  = (const float*)d_in[14];
    float* out = (float*)d_out;

    const int SMEM_GATES = (128 * 68 + 128 * 64) * sizeof(float);  // 67584
    cudaFuncSetAttribute(k_gates, cudaFuncAttributeMaxDynamicSharedMemorySize, SMEM_GATES);
    cudaFuncSetAttribute(k_logits_mma, cudaFuncAttributeMaxDynamicSharedMemorySize, SM_LOG);

    k_init_hc<<<B, 512>>>(V, W_inith, b_inith, W_initc, b_initc);
    k_uv<<<(B * N) / UV_ROWS, 256>>>(V, U_att);
    k_esplit<<<(VOCAB * EMB) / 512, 256>>>(embed);
    k_hw0<<<B, 1024>>>(W_att);        // hW(h0)
    k_att0<<<B, 512>>>(v_att, V);     // ctx(0)

    for (int t = 0; t < STEPS; t++) {
        k_gates<<<dim3(32, 8), 256, SMEM_GATES>>>(embed, y, W_ih, W_hh, t);
        k_lstm_fused<<<dim3(B, 2), 1024>>>(b_ih, b_hh, W_proj, W_att, v_att, V, t & 1);
        k_logits_mma<<<VOCAB / 128, 256, SM_LOG>>>(out, t);
    }
}

// round 14
// speedup vs baseline: 2.5600x; 1.1655x over previous
#include <cuda_runtime.h>
#include <cuda_bf16.h>
#include <math.h>

#define B     64
#define N     196
#define TT    32
#define STEPS 31
#define VOCAB 32000
#define EMB   256
#define HDIM  512
#define VDIM  256
#define ATTD  256
#define G4    2048

// ---------------- scratch (device globals; no allocation) ----------------
__device__ float g_Uv[B * N * ATTD];
__device__ float g_h[B * HDIM];
__device__ float g_c[2][B * HDIM];        // parity double-buffer
__device__ float g_ctx[B * VDIM];
__device__ float g_hW[B * ATTD];          // prologue only
__device__ float g_gpart[8 * B * G4];     // split-K partials for gates (8 chunks)
__device__ __align__(16) __nv_bfloat16 g_hpb[128 * EMB];        // rows 0-63 hi, 64-127 lo
__device__ __align__(16) __nv_bfloat16 g_eh[(size_t)VOCAB * EMB];
__device__ __align__(16) __nv_bfloat16 g_el[(size_t)VOCAB * EMB];

__device__ __forceinline__ float sigmoidf_(float x) { return 1.f / (1.f + expf(-x)); }
__device__ __forceinline__ float tanh_fast(float x) {
    float y;
    asm("tanh.approx.f32 %0, %1;" : "=f"(y) : "f"(x));
    return y;
}

// ---------------- packed f32x2 FMA helpers (SIMT GEMMs) ----------------
typedef unsigned long long ull;
struct Acc44 { ull a[4][2]; };
__device__ __forceinline__ ull fma2(ull a, ull b, ull c) {
    ull d; asm("fma.rn.f32x2 %0, %1, %2, %3;" : "=l"(d) : "l"(a), "l"(b), "l"(c));
    return d;
}
__device__ __forceinline__ ull pack2(float x) {
    ull d; unsigned int xi = __float_as_uint(x);
    asm("mov.b64 %0, {%1, %1};" : "=l"(d) : "r"(xi));
    return d;
}
__device__ __forceinline__ void acc_zero(Acc44& A) {
    #pragma unroll
    for (int i = 0; i < 4; i++) { A.a[i][0] = 0ull; A.a[i][1] = 0ull; }
}
__device__ __forceinline__ void mma44(Acc44& A, float4 xf, ulonglong2 wf) {
    ull h;
    h = pack2(xf.x); A.a[0][0] = fma2(h, wf.x, A.a[0][0]); A.a[0][1] = fma2(h, wf.y, A.a[0][1]);
    h = pack2(xf.y); A.a[1][0] = fma2(h, wf.x, A.a[1][0]); A.a[1][1] = fma2(h, wf.y, A.a[1][1]);
    h = pack2(xf.z); A.a[2][0] = fma2(h, wf.x, A.a[2][0]); A.a[2][1] = fma2(h, wf.y, A.a[2][1]);
    h = pack2(xf.w); A.a[3][0] = fma2(h, wf.x, A.a[3][0]); A.a[3][1] = fma2(h, wf.y, A.a[3][1]);
}
__device__ __forceinline__ float4 unpack44(const Acc44& A, int i) {
    unsigned int l0, h0, l1, h1;
    asm("mov.b64 {%0,%1}, %2;" : "=r"(l0), "=r"(h0) : "l"(A.a[i][0]));
    asm("mov.b64 {%0,%1}, %2;" : "=r"(l1), "=r"(h1) : "l"(A.a[i][1]));
    return make_float4(__uint_as_float(l0), __uint_as_float(h0),
                       __uint_as_float(l1), __uint_as_float(h1));
}

__device__ __forceinline__ unsigned smem_u32(const void* p) {
    unsigned a;
    asm("{ .reg .u64 t; cvta.to.shared.u64 t, %1; cvt.u32.u64 %0, t; }" : "=r"(a) : "l"(p));
    return a;
}

// ---------------- init: feat_mean -> h0, c0 ----------------
__global__ void k_init_hc(const float* __restrict__ V,
                          const float* __restrict__ Wh, const float* __restrict__ bh,
                          const float* __restrict__ Wc, const float* __restrict__ bc) {
    int b = blockIdx.x, tid = threadIdx.x;
    __shared__ float fm[VDIM];
    if (tid < VDIM) {
        const float* vp = V + (size_t)b * N * VDIM + tid;
        float s = 0.f;
        for (int n = 0; n < N; n++) s += vp[(size_t)n * VDIM];
        fm[tid] = s * (1.f / (float)N);
    }
    __syncthreads();
    int j = tid;
    float ah = bh[j], ac = bc[j];
    #pragma unroll 4
    for (int v = 0; v < VDIM; v++) {
        float f = fm[v];
        ah += f * Wh[(size_t)v * HDIM + j];
        ac += f * Wc[(size_t)v * HDIM + j];
    }
    g_h[b * HDIM + j] = tanhf(ah);
    g_c[0][b * HDIM + j] = tanhf(ac);
}

// ---------------- hW(h0) for step 0: 4 threads/j ----------------
__global__ void k_hw0(const float* __restrict__ Watt) {
    int b = blockIdx.x, tid = threadIdx.x;
    __shared__ float hs[HDIM];
    __shared__ float red[1024];
    if (tid < 512) hs[tid] = g_h[b * HDIM + tid];
    __syncthreads();
    int jl = tid & 255, kh = tid >> 8;
    const float* W = Watt + (size_t)(kh * 128) * ATTD + jl;
    const float* hp = hs + kh * 128;
    float a0 = 0.f, a1 = 0.f, a2 = 0.f, a3 = 0.f;
    #pragma unroll 8
    for (int k = 0; k < 128; k += 4) {
        a0 += hp[k]     * W[(size_t)k * ATTD];
        a1 += hp[k + 1] * W[(size_t)(k + 1) * ATTD];
        a2 += hp[k + 2] * W[(size_t)(k + 2) * ATTD];
        a3 += hp[k + 3] * W[(size_t)(k + 3) * ATTD];
    }
    red[tid] = (a0 + a1) + (a2 + a3);
    __syncthreads();
    if (tid < 256)
        g_hW[b * ATTD + jl] = (red[jl] + red[jl + 256]) + (red[jl + 512] + red[jl + 768]);
}

// ---------------- Uv = V @ U_att (once) ----------------
#define UV_ROWS 16
__global__ void k_uv(const float* __restrict__ V, const float* __restrict__ U) {
    __shared__ float Vs[UV_ROWS * VDIM];
    int r0 = blockIdx.x * UV_ROWS;
    int tid = threadIdx.x;
    for (int i = tid; i < UV_ROWS * VDIM; i += 256)
        Vs[i] = V[(size_t)r0 * VDIM + i];
    __syncthreads();
    float acc[UV_ROWS];
    #pragma unroll
    for (int i = 0; i < UV_ROWS; i++) acc[i] = 0.f;
    int a = tid;
    #pragma unroll 4
    for (int v = 0; v < VDIM; v++) {
        float u = U[(size_t)v * ATTD + a];
        #pragma unroll
        for (int i = 0; i < UV_ROWS; i++) acc[i] += Vs[i * VDIM + v] * u;
    }
    #pragma unroll
    for (int i = 0; i < UV_ROWS; i++)
        g_Uv[(size_t)(r0 + i) * ATTD + a] = acc[i];
}

// ---------------- embed -> bf16 hi/lo (once) ----------------
__global__ void k_esplit(const float* __restrict__ e) {
    size_t i = ((size_t)blockIdx.x * 256 + threadIdx.x) * 2;
    float2 v = *(const float2*)(e + i);
    __nv_bfloat16 h0 = __float2bfloat16(v.x);
    __nv_bfloat16 h1 = __float2bfloat16(v.y);
    __nv_bfloat16 l0 = __float2bfloat16(v.x - __bfloat162float(h0));
    __nv_bfloat16 l1 = __float2bfloat16(v.y - __bfloat162float(h1));
    *(__nv_bfloat162*)(g_eh + i) = __nv_bfloat162(h0, h1);
    *(__nv_bfloat162*)(g_el + i) = __nv_bfloat162(l0, l1);
}

// ---------------- prologue attention (ctx for step 0, reads g_hW) ----------------
__global__ void k_att0(const float* __restrict__ vatt, const float* __restrict__ V) {
    int b = blockIdx.x, tid = threadIdx.x;
    __shared__ float hWs[ATTD];
    __shared__ float vs[ATTD];
    __shared__ float es[256];
    __shared__ float red[256];
    __shared__ float ctxp[512];
    if (tid < 256) {
        hWs[tid] = g_hW[b * ATTD + tid];
        vs[tid] = vatt[tid];
    }
    __syncthreads();
    int warp = tid >> 5, lane = tid & 31;
    for (int n = warp; n < N; n += 16) {
        const float* uv = g_Uv + (size_t)(b * N + n) * ATTD;
        float p = 0.f;
        #pragma unroll
        for (int j = 0; j < 8; j++) {
            int a = lane + 32 * j;
            p += tanh_fast(hWs[a] + uv[a]) * vs[a];
        }
        #pragma unroll
        for (int off = 16; off > 0; off >>= 1)
            p += __shfl_down_sync(0xffffffffu, p, off);
        if (lane == 0) es[n] = p;
    }
    __syncthreads();
    float v = (tid < N) ? es[tid] : -INFINITY;
    if (tid < 256) red[tid] = v;
    __syncthreads();
    for (int s = 128; s > 0; s >>= 1) {
        if (tid < s) red[tid] = fmaxf(red[tid], red[tid + s]);
        __syncthreads();
    }
    float mx = red[0];
    __syncthreads();
    float ex = (tid < N) ? expf(v - mx) : 0.f;
    if (tid < 256) red[tid] = ex;
    __syncthreads();
    for (int s = 128; s > 0; s >>= 1) {
        if (tid < s) red[tid] += red[tid + s];
        __syncthreads();
    }
    float inv = 1.f / red[0];
    __syncthreads();
    if (tid < N) es[tid] = ex * inv;
    __syncthreads();
    int half = tid >> 8, vd = tid & 255;
    const float* vp = V + (size_t)b * N * VDIM + (size_t)half * 98 * VDIM + vd;
    float acc = 0.f;
    #pragma unroll 7
    for (int n = 0; n < 98; n++) acc += es[half * 98 + n] * vp[(size_t)n * VDIM];
    ctxp[tid] = acc;
    __syncthreads();
    if (tid < 256) g_ctx[b * VDIM + tid] = ctxp[tid] + ctxp[tid + 256];
}

// ================= gates body (split-K x8), 256 threads =================
__device__ __forceinline__ void gates_body(char* smc, const float* __restrict__ embed,
                                           const int* __restrict__ y,
                                           const float* __restrict__ Wih,
                                           const float* __restrict__ Whh,
                                           int t, int j0, int kc) {
    float* Xs = (float*)smc;                 // [128 kk][68 pad]
    float* Ws = (float*)smc + 128 * 68;      // [128 kk][64 jj]
    int tid = threadIdx.x;

    for (int idx = tid; idx < B * 128; idx += 256) {
        int kk = idx & 127, bb = idx >> 7;
        int gk = kc * 128 + kk;
        float x;
        if (gk < 256)      x = embed[(size_t)y[bb * TT + t] * EMB + gk];
        else if (gk < 512) x = g_ctx[bb * VDIM + (gk - 256)];
        else               x = g_h[bb * HDIM + (gk - 512)];
        Xs[kk * 68 + bb] = x;
    }
    const float* W = (kc < 4) ? (Wih + (size_t)(kc * 128) * G4)
                              : (Whh + (size_t)((kc - 4) * 128) * G4);
    for (int idx = tid; idx < 128 * 64; idx += 256) {
        int kk = idx >> 6, jj = idx & 63;
        Ws[idx] = W[(size_t)kk * G4 + j0 + jj];
    }
    __syncthreads();

    int tx = tid & 15, ty = tid >> 4;
    Acc44 A; acc_zero(A);
    #pragma unroll 4
    for (int kk = 0; kk < 128; kk++) {
        float4 xf = *(const float4*)&Xs[kk * 68 + ty * 4];
        ulonglong2 wf = *(const ulonglong2*)&Ws[kk * 64 + tx * 4];
        mma44(A, xf, wf);
    }
    float* gp = g_gpart + (size_t)kc * B * G4;
    #pragma unroll
    for (int i = 0; i < 4; i++) {
        int bb = ty * 4 + i;
        *(float4*)&gp[(size_t)bb * G4 + j0 + tx * 4] = unpack44(A, i);
    }
}

// prologue-only standalone gates
__global__ void k_gates(const float* __restrict__ embed, const int* __restrict__ y,
                        const float* __restrict__ Wih, const float* __restrict__ Whh, int t) {
    extern __shared__ char smc[];
    gates_body(smc, embed, y, Wih, Whh, t, (blockIdx.x & 31) * 64, blockIdx.x >> 5);
}

// ---------------- fused LSTM + proj GEMV + attention(t+1) ----------------
// grid = dim3(B, 2), block = 1024
__global__ void k_lstm_fused(const float* __restrict__ bih, const float* __restrict__ bhh,
                             const float* __restrict__ Wproj, const float* __restrict__ Watt,
                             const float* __restrict__ vatt, const float* __restrict__ V,
                             int parity) {
    int b = blockIdx.x, jc = blockIdx.y, tid = threadIdx.x;
    __shared__ float hs[HDIM];
    __shared__ float red[1024];
    __shared__ float hWs[ATTD];
    __shared__ float vs[ATTD];
    __shared__ float es[256];
    __shared__ float sred[256];

    if (tid < 512) {
        int j = tid;
        float gi = bih[j]        + bhh[j];
        float gf = bih[512 + j]  + bhh[512 + j];
        float gg = bih[1024 + j] + bhh[1024 + j];
        float go = bih[1536 + j] + bhh[1536 + j];
        #pragma unroll
        for (int kc = 0; kc < 8; kc++) {
            const float* gp = g_gpart + (size_t)kc * B * G4 + (size_t)b * G4;
            gi += gp[j]; gf += gp[512 + j]; gg += gp[1024 + j]; go += gp[1536 + j];
        }
        float c = sigmoidf_(gf) * g_c[parity][b * HDIM + j] + sigmoidf_(gi) * tanhf(gg);
        float h = sigmoidf_(go) * tanhf(c);
        if (jc == 0) {
            g_c[parity ^ 1][b * HDIM + j] = c;
            g_h[b * HDIM + j] = h;
        }
        hs[j] = h;
    }
    __syncthreads();

    int jl = tid & 255, kh = tid >> 8;
    const float* W = ((jc == 0) ? Wproj : Watt) + (size_t)(kh * 128) * 256 + jl;
    const float* hp = hs + kh * 128;
    float a0 = 0.f, a1 = 0.f, a2 = 0.f, a3 = 0.f;
    #pragma unroll 8
    for (int k = 0; k < 128; k += 4) {
        a0 += hp[k]     * W[(size_t)k * 256];
        a1 += hp[k + 1] * W[(size_t)(k + 1) * 256];
        a2 += hp[k + 2] * W[(size_t)(k + 2) * 256];
        a3 += hp[k + 3] * W[(size_t)(k + 3) * 256];
    }
    red[tid] = (a0 + a1) + (a2 + a3);
    __syncthreads();
    if (tid < 256) {
        float s = (red[jl] + red[jl + 256]) + (red[jl + 512] + red[jl + 768]);
        if (jc == 0) {
            __nv_bfloat16 hi = __float2bfloat16(s);
            __nv_bfloat16 lo = __float2bfloat16(s - __bfloat162float(hi));
            g_hpb[b * EMB + jl] = hi;
            g_hpb[(64 + b) * EMB + jl] = lo;
        } else {
            hWs[jl] = s;
            vs[jl] = vatt[jl];
        }
    }
    if (jc == 0) return;

    // ---- attention for next step ----
    __syncthreads();
    int warp = tid >> 5, lane = tid & 31;
    for (int n = warp; n < N; n += 32) {
        const float* uv = g_Uv + (size_t)(b * N + n) * ATTD;
        float p = 0.f;
        #pragma unroll
        for (int j = 0; j < 8; j++) {
            int a = lane + 32 * j;
            p += tanh_fast(hWs[a] + uv[a]) * vs[a];
        }
        #pragma unroll
        for (int off = 16; off > 0; off >>= 1)
            p += __shfl_down_sync(0xffffffffu, p, off);
        if (lane == 0) es[n] = p;
    }
    __syncthreads();
    float v = (tid < N) ? es[tid] : -INFINITY;
    if (tid < 256) sred[tid] = v;
    __syncthreads();
    for (int s = 128; s > 0; s >>= 1) {
        if (tid < s) sred[tid] = fmaxf(sred[tid], sred[tid + s]);
        __syncthreads();
    }
    float mx = sred[0];
    __syncthreads();
    float ex = (tid < N) ? expf(v - mx) : 0.f;
    if (tid < 256) sred[tid] = ex;
    __syncthreads();
    for (int s = 128; s > 0; s >>= 1) {
        if (tid < s) sred[tid] += sred[tid + s];
        __syncthreads();
    }
    float inv = 1.f / sred[0];
    __syncthreads();
    if (tid < N) es[tid] = ex * inv;
    __syncthreads();
    int q = tid >> 8, vd = tid & 255;
    const float* vp = V + (size_t)b * N * VDIM + (size_t)q * 49 * VDIM + vd;
    float acc = 0.f;
    #pragma unroll 7
    for (int n = 0; n < 49; n++) acc += es[q * 49 + n] * vp[(size_t)n * VDIM];
    red[tid] = acc;
    __syncthreads();
    if (tid < 256)
        g_ctx[b * VDIM + vd] = (red[vd] + red[vd + 256]) + (red[vd + 512] + red[vd + 768]);
}

// ================= logits body (mma.sync bf16 hi/lo), 256 threads =================
#define SA  0
#define SBH 32768
#define SBL (SBH + 34816)
#define SM_LOG (SBL + 34816)   // 102400

__device__ __forceinline__ void logits_body(char* smc, float* __restrict__ out,
                                            int t, int v0) {
    const unsigned sb = smem_u32(smc);
    int tid = threadIdx.x;
    int wid = tid >> 5, lane = tid & 31;
    int wr = wid & 3, wc = wid >> 2;
    bool hiwarp = (wr < 2);

    float d[16][4];
    #pragma unroll
    for (int f = 0; f < 16; f++) { d[f][0] = d[f][1] = d[f][2] = d[f][3] = 0.f; }

    int bmat = lane >> 3, brow = lane & 7;
    int bn_local = ((bmat >> 1) << 3) + brow;
    unsigned bkoff = (unsigned)((bmat & 1) << 3) * 2;

    #pragma unroll
    for (int kc = 0; kc < 2; kc++) {
        for (int i = tid; i < 2048; i += 256) {
            int m = i >> 4, u = i & 15;
            *(uint4*)(smc + SA + m * 256 + ((u ^ (m & 7)) << 4)) =
                *(const uint4*)((const char*)g_hpb + (size_t)m * 512 + kc * 256 + u * 16);
        }
        for (int i = tid; i < 2048; i += 256) {
            int n = i >> 4, u = i & 15;
            size_t go = (size_t)(v0 + n) * 512 + kc * 256 + u * 16;
            *(uint4*)(smc + SBH + n * 272 + u * 16) = *(const uint4*)((const char*)g_eh + go);
            *(uint4*)(smc + SBL + n * 272 + u * 16) = *(const uint4*)((const char*)g_el + go);
        }
        __syncthreads();

        #pragma unroll
        for (int ks = 0; ks < 8; ks++) {
            unsigned a[2][4];
            #pragma unroll
            for (int mi = 0; mi < 2; mi++) {
                int m = wr * 32 + mi * 16 + ((lane >> 3) & 1) * 8 + (lane & 7);
                int u = ks * 2 + (lane >> 4);
                unsigned addr = sb + SA + m * 256 + ((u ^ (m & 7)) << 4);
                asm volatile(
                    "ldmatrix.sync.aligned.m8n8.x4.shared.b16 {%0,%1,%2,%3}, [%4];"
                    : "=r"(a[mi][0]), "=r"(a[mi][1]), "=r"(a[mi][2]), "=r"(a[mi][3])
                    : "r"(addr));
            }
            unsigned bko = (unsigned)(ks * 32) + bkoff;
            #pragma unroll
            for (int np = 0; np < 4; np++) {
                unsigned brow_addr = sb + SBH +
                    (unsigned)((wc * 64 + np * 16 + bn_local) * 272) + bko;
                unsigned bh[4];
                asm volatile(
                    "ldmatrix.sync.aligned.m8n8.x4.shared.b16 {%0,%1,%2,%3}, [%4];"
                    : "=r"(bh[0]), "=r"(bh[1]), "=r"(bh[2]), "=r"(bh[3])
                    : "r"(brow_addr));
                #pragma unroll
                for (int half = 0; half < 2; half++) {
                    int f0 = np * 2 + half;
                    #pragma unroll
                    for (int mi = 0; mi < 2; mi++) {
                        int f = mi * 8 + f0;
                        asm volatile(
                            "mma.sync.aligned.m16n8k16.row.col.f32.bf16.bf16.f32 "
                            "{%0,%1,%2,%3}, {%4,%5,%6,%7}, {%8,%9}, {%0,%1,%2,%3};"
                            : "+f"(d[f][0]), "+f"(d[f][1]), "+f"(d[f][2]), "+f"(d[f][3])
                            : "r"(a[mi][0]), "r"(a[mi][1]), "r"(a[mi][2]), "r"(a[mi][3]),
                              "r"(bh[half * 2]), "r"(bh[half * 2 + 1]));
                    }
                }
                if (hiwarp) {
                    unsigned blo_addr = brow_addr + (SBL - SBH);
                    unsigned bl[4];
                    asm volatile(
                        "ldmatrix.sync.aligned.m8n8.x4.shared.b16 {%0,%1,%2,%3}, [%4];"
                        : "=r"(bl[0]), "=r"(bl[1]), "=r"(bl[2]), "=r"(bl[3])
                        : "r"(blo_addr));
                    #pragma unroll
                    for (int half = 0; half < 2; half++) {
                        int f0 = np * 2 + half;
                        #pragma unroll
                        for (int mi = 0; mi < 2; mi++) {
                            int f = mi * 8 + f0;
                            asm volatile(
                                "mma.sync.aligned.m16n8k16.row.col.f32.bf16.bf16.f32 "
                                "{%0,%1,%2,%3}, {%4,%5,%6,%7}, {%8,%9}, {%0,%1,%2,%3};"
                                : "+f"(d[f][0]), "+f"(d[f][1]), "+f"(d[f][2]), "+f"(d[f][3])
                                : "r"(a[mi][0]), "r"(a[mi][1]), "r"(a[mi][2]), "r"(a[mi][3]),
                                  "r"(bl[half * 2]), "r"(bl[half * 2 + 1]));
                        }
                    }
                }
            }
        }
        __syncthreads();
    }

    float* epi = (float*)(smc + SA);
    if (wr >= 2) {
        #pragma unroll
        for (int mi = 0; mi < 2; mi++) {
            int r0 = (wr - 2) * 32 + mi * 16 + (lane >> 2);
            #pragma unroll
            for (int nf = 0; nf < 8; nf++) {
                int f = mi * 8 + nf;
                int col = wc * 64 + nf * 8 + (lane & 3) * 2;
                epi[r0 * 128 + col]           = d[f][0];
                epi[r0 * 128 + col + 1]       = d[f][1];
                epi[(r0 + 8) * 128 + col]     = d[f][2];
                epi[(r0 + 8) * 128 + col + 1] = d[f][3];
            }
        }
    }
    __syncthreads();
    if (wr < 2) {
        #pragma unroll
        for (int mi = 0; mi < 2; mi++) {
            int b0 = wr * 32 + mi * 16 + (lane >> 2);
            #pragma unroll
            for (int nf = 0; nf < 8; nf++) {
                int f = mi * 8 + nf;
                int col = wc * 64 + nf * 8 + (lane & 3) * 2;
                float2 r0v = make_float2(d[f][0] + epi[b0 * 128 + col],
                                         d[f][1] + epi[b0 * 128 + col + 1]);
                float2 r1v = make_float2(d[f][2] + epi[(b0 + 8) * 128 + col],
                                         d[f][3] + epi[(b0 + 8) * 128 + col + 1]);
                *(float2*)(out + ((size_t)b0 * STEPS + t) * VOCAB + v0 + col) = r0v;
                *(float2*)(out + ((size_t)(b0 + 8) * STEPS + t) * VOCAB + v0 + col) = r1v;
            }
        }
    }
}

// ================= combo: logits(t) [blocks 0..249] + gates(t+1) [250..505] =================
__global__ void __launch_bounds__(256, 2) k_combo(float* __restrict__ out, int t,
                                                  const float* __restrict__ embed,
                                                  const int* __restrict__ y,
                                                  const float* __restrict__ Wih,
                                                  const float* __restrict__ Whh) {
    extern __shared__ char smc[];
    if (blockIdx.x < 250) {
        logits_body(smc, out, t, blockIdx.x * 128);
    } else {
        int idx = blockIdx.x - 250;
        // gates for step t+1 (t+1 == STEPS computes harmlessly; never consumed)
        gates_body(smc, embed, y, Wih, Whh, t + 1, (idx & 31) * 64, idx >> 5);
    }
}

// ---------------- launch ----------------
extern "C" void kernel_launch(void* const* d_in, const int* in_sizes, int n_in,
                              void* d_out, int out_size) {
    const float* V      = (const float*)d_in[0];
    const int*   y      = (const int*)  d_in[1];
    const float* embed  = (const float*)d_in[2];
    const float* W_att  = (const float*)d_in[3];
    const float* U_att  = (const float*)d_in[4];
    const float* v_att  = (const float*)d_in[5];
    const float* W_ih   = (const float*)d_in[6];
    const float* W_hh   = (const float*)d_in[7];
    const float* b_ih   = (const float*)d_in[8];
    const float* b_hh   = (const float*)d_in[9];
    const float* W_inith = (const float*)d_in[10];
    const float* b_inith = (const float*)d_in[11];
    const float* W_initc = (const float*)d_in[12];
    const float* b_initc = (const float*)d_in[13];
    const float* W_proj  = (const float*)d_in[14];
    float* out = (float*)d_out;

    const int SMEM_GATES = (128 * 68 + 128 * 64) * sizeof(float);  // 67584
    cudaFuncSetAttribute(k_gates, cudaFuncAttributeMaxDynamicSharedMemorySize, SMEM_GATES);
    cudaFuncSetAttribute(k_combo, cudaFuncAttributeMaxDynamicSharedMemorySize, SM_LOG);

    k_init_hc<<<B, 512>>>(V, W_inith, b_inith, W_initc, b_initc);
    k_uv<<<(B * N) / UV_ROWS, 256>>>(V, U_att);
    k_esplit<<<(VOCAB * EMB) / 512, 256>>>(embed);
    k_hw0<<<B, 1024>>>(W_att);                               // hW(h0)
    k_att0<<<B, 512>>>(v_att, V);                            // ctx(0)
    k_gates<<<256, 256, SMEM_GATES>>>(embed, y, W_ih, W_hh, 0);  // gates(0)

    for (int t = 0; t < STEPS; t++) {
        k_lstm_fused<<<dim3(B, 2), 1024>>>(b_ih, b_hh, W_proj, W_att, v_att, V, t & 1);
        k_combo<<<506, 256, SM_LOG>>>(out, t, embed, y, W_ih, W_hh);
    }
}

// round 15
// speedup vs baseline: 2.5647x; 1.0019x over previous
#include <cuda_runtime.h>
#include <cuda_bf16.h>
#include <math.h>

#define B     64
#define N     196
#define TT    32
#define STEPS 31
#define VOCAB 32000
#define EMB   256
#define HDIM  512
#define VDIM  256
#define ATTD  256
#define G4    2048

// ---------------- scratch (device globals; no allocation) ----------------
__device__ float g_Uv[B * N * ATTD];
__device__ float g_h[B * HDIM];
__device__ float g_c[2][B * HDIM];        // parity double-buffer
__device__ float g_ctx[B * VDIM];
__device__ float g_hW[B * ATTD];          // prologue only
__device__ float g_gpart[8 * B * G4];     // split-K partials for gates (8 chunks)
__device__ __align__(16) __nv_bfloat16 g_hpb[128 * EMB];        // rows 0-63 hi, 64-127 lo
__device__ __align__(16) __nv_bfloat16 g_eh[(size_t)VOCAB * EMB];
__device__ __align__(16) __nv_bfloat16 g_el[(size_t)VOCAB * EMB];
__device__ unsigned g_flag_hp;            // jc=0 producer arrivals (monotonic)
__device__ unsigned g_flag_all;           // all producer arrivals (monotonic)

__device__ __forceinline__ float sigmoidf_(float x) { return 1.f / (1.f + expf(-x)); }
__device__ __forceinline__ float tanh_fast(float x) {
    float y;
    asm("tanh.approx.f32 %0, %1;" : "=f"(y) : "f"(x));
    return y;
}

// ---------------- packed f32x2 FMA helpers (SIMT GEMMs) ----------------
typedef unsigned long long ull;
struct Acc44 { ull a[4][2]; };
__device__ __forceinline__ ull fma2(ull a, ull b, ull c) {
    ull d; asm("fma.rn.f32x2 %0, %1, %2, %3;" : "=l"(d) : "l"(a), "l"(b), "l"(c));
    return d;
}
__device__ __forceinline__ ull pack2(float x) {
    ull d; unsigned int xi = __float_as_uint(x);
    asm("mov.b64 %0, {%1, %1};" : "=l"(d) : "r"(xi));
    return d;
}
__device__ __forceinline__ void acc_zero(Acc44& A) {
    #pragma unroll
    for (int i = 0; i < 4; i++) { A.a[i][0] = 0ull; A.a[i][1] = 0ull; }
}
__device__ __forceinline__ void mma44(Acc44& A, float4 xf, ulonglong2 wf) {
    ull h;
    h = pack2(xf.x); A.a[0][0] = fma2(h, wf.x, A.a[0][0]); A.a[0][1] = fma2(h, wf.y, A.a[0][1]);
    h = pack2(xf.y); A.a[1][0] = fma2(h, wf.x, A.a[1][0]); A.a[1][1] = fma2(h, wf.y, A.a[1][1]);
    h = pack2(xf.z); A.a[2][0] = fma2(h, wf.x, A.a[2][0]); A.a[2][1] = fma2(h, wf.y, A.a[2][1]);
    h = pack2(xf.w); A.a[3][0] = fma2(h, wf.x, A.a[3][0]); A.a[3][1] = fma2(h, wf.y, A.a[3][1]);
}
__device__ __forceinline__ float4 unpack44(const Acc44& A, int i) {
    unsigned int l0, h0, l1, h1;
    asm("mov.b64 {%0,%1}, %2;" : "=r"(l0), "=r"(h0) : "l"(A.a[i][0]));
    asm("mov.b64 {%0,%1}, %2;" : "=r"(l1), "=r"(h1) : "l"(A.a[i][1]));
    return make_float4(__uint_as_float(l0), __uint_as_float(h0),
                       __uint_as_float(l1), __uint_as_float(h1));
}

__device__ __forceinline__ unsigned smem_u32(const void* p) {
    unsigned a;
    asm("{ .reg .u64 t; cvta.to.shared.u64 t, %1; cvt.u32.u64 %0, t; }" : "=r"(a) : "l"(p));
    return a;
}

// acquire-spin on a monotonic flag (tid 0 spins, block syncs after)
__device__ __forceinline__ void wait_flag(unsigned* f, unsigned target) {
    if (threadIdx.x == 0) {
        unsigned v;
        for (;;) {
            asm volatile("ld.acquire.gpu.u32 %0, [%1];" : "=r"(v) : "l"(f) : "memory");
            if (v >= target) break;
            __nanosleep(64);
        }
    }
    __syncthreads();
}

// ---------------- init: feat_mean -> h0, c0 ----------------
__global__ void k_init_hc(const float* __restrict__ V,
                          const float* __restrict__ Wh, const float* __restrict__ bh,
                          const float* __restrict__ Wc, const float* __restrict__ bc) {
    int b = blockIdx.x, tid = threadIdx.x;
    __shared__ float fm[VDIM];
    if (tid < VDIM) {
        const float* vp = V + (size_t)b * N * VDIM + tid;
        float s = 0.f;
        for (int n = 0; n < N; n++) s += vp[(size_t)n * VDIM];
        fm[tid] = s * (1.f / (float)N);
    }
    __syncthreads();
    int j = tid;
    float ah = bh[j], ac = bc[j];
    #pragma unroll 4
    for (int v = 0; v < VDIM; v++) {
        float f = fm[v];
        ah += f * Wh[(size_t)v * HDIM + j];
        ac += f * Wc[(size_t)v * HDIM + j];
    }
    g_h[b * HDIM + j] = tanhf(ah);
    g_c[0][b * HDIM + j] = tanhf(ac);
}

// reset flags (start of every capture/replay)
__global__ void k_reset() { g_flag_hp = 0; g_flag_all = 0; }

// ---------------- hW(h0) for step 0 ----------------
__global__ void k_hw0(const float* __restrict__ Watt) {
    int b = blockIdx.x, tid = threadIdx.x;
    __shared__ float hs[HDIM];
    __shared__ float red[1024];
    if (tid < 512) hs[tid] = g_h[b * HDIM + tid];
    __syncthreads();
    int jl = tid & 255, kh = tid >> 8;
    const float* W = Watt + (size_t)(kh * 128) * ATTD + jl;
    const float* hp = hs + kh * 128;
    float a0 = 0.f, a1 = 0.f, a2 = 0.f, a3 = 0.f;
    #pragma unroll 8
    for (int k = 0; k < 128; k += 4) {
        a0 += hp[k]     * W[(size_t)k * ATTD];
        a1 += hp[k + 1] * W[(size_t)(k + 1) * ATTD];
        a2 += hp[k + 2] * W[(size_t)(k + 2) * ATTD];
        a3 += hp[k + 3] * W[(size_t)(k + 3) * ATTD];
    }
    red[tid] = (a0 + a1) + (a2 + a3);
    __syncthreads();
    if (tid < 256)
        g_hW[b * ATTD + jl] = (red[jl] + red[jl + 256]) + (red[jl + 512] + red[jl + 768]);
}

// ---------------- Uv = V @ U_att (once) ----------------
#define UV_ROWS 16
__global__ void k_uv(const float* __restrict__ V, const float* __restrict__ U) {
    __shared__ float Vs[UV_ROWS * VDIM];
    int r0 = blockIdx.x * UV_ROWS;
    int tid = threadIdx.x;
    for (int i = tid; i < UV_ROWS * VDIM; i += 256)
        Vs[i] = V[(size_t)r0 * VDIM + i];
    __syncthreads();
    float acc[UV_ROWS];
    #pragma unroll
    for (int i = 0; i < UV_ROWS; i++) acc[i] = 0.f;
    int a = tid;
    #pragma unroll 4
    for (int v = 0; v < VDIM; v++) {
        float u = U[(size_t)v * ATTD + a];
        #pragma unroll
        for (int i = 0; i < UV_ROWS; i++) acc[i] += Vs[i * VDIM + v] * u;
    }
    #pragma unroll
    for (int i = 0; i < UV_ROWS; i++)
        g_Uv[(size_t)(r0 + i) * ATTD + a] = acc[i];
}

// ---------------- embed -> bf16 hi/lo (once) ----------------
__global__ void k_esplit(const float* __restrict__ e) {
    size_t i = ((size_t)blockIdx.x * 256 + threadIdx.x) * 2;
    float2 v = *(const float2*)(e + i);
    __nv_bfloat16 h0 = __float2bfloat16(v.x);
    __nv_bfloat16 h1 = __float2bfloat16(v.y);
    __nv_bfloat16 l0 = __float2bfloat16(v.x - __bfloat162float(h0));
    __nv_bfloat16 l1 = __float2bfloat16(v.y - __bfloat162float(h1));
    *(__nv_bfloat162*)(g_eh + i) = __nv_bfloat162(h0, h1);
    *(__nv_bfloat162*)(g_el + i) = __nv_bfloat162(l0, l1);
}

// ---------------- prologue attention (ctx for step 0, reads g_hW) ----------------
__global__ void k_att0(const float* __restrict__ vatt, const float* __restrict__ V) {
    int b = blockIdx.x, tid = threadIdx.x;
    __shared__ float hWs[ATTD];
    __shared__ float vs[ATTD];
    __shared__ float es[256];
    __shared__ float red[256];
    __shared__ float ctxp[512];
    if (tid < 256) {
        hWs[tid] = g_hW[b * ATTD + tid];
        vs[tid] = vatt[tid];
    }
    __syncthreads();
    int warp = tid >> 5, lane = tid & 31;
    for (int n = warp; n < N; n += 16) {
        const float* uv = g_Uv + (size_t)(b * N + n) * ATTD;
        float p = 0.f;
        #pragma unroll
        for (int j = 0; j < 8; j++) {
            int a = lane + 32 * j;
            p += tanh_fast(hWs[a] + uv[a]) * vs[a];
        }
        #pragma unroll
        for (int off = 16; off > 0; off >>= 1)
            p += __shfl_down_sync(0xffffffffu, p, off);
        if (lane == 0) es[n] = p;
    }
    __syncthreads();
    float v = (tid < N) ? es[tid] : -INFINITY;
    if (tid < 256) red[tid] = v;
    __syncthreads();
    for (int s = 128; s > 0; s >>= 1) {
        if (tid < s) red[tid] = fmaxf(red[tid], red[tid + s]);
        __syncthreads();
    }
    float mx = red[0];
    __syncthreads();
    float ex = (tid < N) ? expf(v - mx) : 0.f;
    if (tid < 256) red[tid] = ex;
    __syncthreads();
    for (int s = 128; s > 0; s >>= 1) {
        if (tid < s) red[tid] += red[tid + s];
        __syncthreads();
    }
    float inv = 1.f / red[0];
    __syncthreads();
    if (tid < N) es[tid] = ex * inv;
    __syncthreads();
    int half = tid >> 8, vd = tid & 255;
    const float* vp = V + (size_t)b * N * VDIM + (size_t)half * 98 * VDIM + vd;
    float acc = 0.f;
    #pragma unroll 7
    for (int n = 0; n < 98; n++) acc += es[half * 98 + n] * vp[(size_t)n * VDIM];
    ctxp[tid] = acc;
    __syncthreads();
    if (tid < 256) g_ctx[b * VDIM + tid] = ctxp[tid] + ctxp[tid + 256];
}

// ================= gates body (split-K x8), 256 threads =================
// wait_target > 0: prefetch Ws, spin on g_flag_all, then load Xs.
__device__ __forceinline__ void gates_body(char* smc, const float* __restrict__ embed,
                                           const int* __restrict__ y,
                                           const float* __restrict__ Wih,
                                           const float* __restrict__ Whh,
                                           int t, int j0, int kc, unsigned wait_target) {
    float* Xs = (float*)smc;                 // [128 kk][68 pad]
    float* Ws = (float*)smc + 128 * 68;      // [128 kk][64 jj]
    int tid = threadIdx.x;

    const float* W = (kc < 4) ? (Wih + (size_t)(kc * 128) * G4)
                              : (Whh + (size_t)((kc - 4) * 128) * G4);
    for (int idx = tid; idx < 128 * 64; idx += 256) {
        int kk = idx >> 6, jj = idx & 63;
        Ws[idx] = W[(size_t)kk * G4 + j0 + jj];
    }
    if (wait_target) wait_flag(&g_flag_all, wait_target);

    for (int idx = tid; idx < B * 128; idx += 256) {
        int kk = idx & 127, bb = idx >> 7;
        int gk = kc * 128 + kk;
        float x;
        if (gk < 256)      x = embed[(size_t)y[bb * TT + t] * EMB + gk];
        else if (gk < 512) x = g_ctx[bb * VDIM + (gk - 256)];
        else               x = g_h[bb * HDIM + (gk - 512)];
        Xs[kk * 68 + bb] = x;
    }
    __syncthreads();

    int tx = tid & 15, ty = tid >> 4;
    Acc44 A; acc_zero(A);
    #pragma unroll 4
    for (int kk = 0; kk < 128; kk++) {
        float4 xf = *(const float4*)&Xs[kk * 68 + ty * 4];
        ulonglong2 wf = *(const ulonglong2*)&Ws[kk * 64 + tx * 4];
        mma44(A, xf, wf);
    }
    float* gp = g_gpart + (size_t)kc * B * G4;
    #pragma unroll
    for (int i = 0; i < 4; i++) {
        int bb = ty * 4 + i;
        *(float4*)&gp[(size_t)bb * G4 + j0 + tx * 4] = unpack44(A, i);
    }
}

// prologue-only standalone gates (no wait)
__global__ void k_gates(const float* __restrict__ embed, const int* __restrict__ y,
                        const float* __restrict__ Wih, const float* __restrict__ Whh, int t) {
    extern __shared__ char smc[];
    gates_body(smc, embed, y, Wih, Whh, t, (blockIdx.x & 31) * 64, blockIdx.x >> 5, 0u);
}

// ================= producer body: LSTM + proj GEMV (+ attention jc=1), 256 threads =================
__device__ __forceinline__ void producer_body(char* smc,
                                              const float* __restrict__ bih,
                                              const float* __restrict__ bhh,
                                              const float* __restrict__ Wproj,
                                              const float* __restrict__ Watt,
                                              const float* __restrict__ vatt,
                                              const float* __restrict__ V,
                                              int parity, int b, int jc) {
    float* hs  = (float*)smc;        // [512]
    float* red = hs + 512;           // [256]
    float* vs  = red + 256;          // [256]
    float* es  = vs + 256;           // [256]
    int tid = threadIdx.x;

    // LSTM pointwise: 2 j's per thread
    #pragma unroll
    for (int jj = 0; jj < 2; jj++) {
        int j = tid + jj * 256;
        float gi = bih[j]        + bhh[j];
        float gf = bih[512 + j]  + bhh[512 + j];
        float gg = bih[1024 + j] + bhh[1024 + j];
        float go = bih[1536 + j] + bhh[1536 + j];
        #pragma unroll
        for (int kc = 0; kc < 8; kc++) {
            const float* gp = g_gpart + (size_t)kc * B * G4 + (size_t)b * G4;
            gi += gp[j]; gf += gp[512 + j]; gg += gp[1024 + j]; go += gp[1536 + j];
        }
        float c = sigmoidf_(gf) * g_c[parity][b * HDIM + j] + sigmoidf_(gi) * tanhf(gg);
        float h = sigmoidf_(go) * tanhf(c);
        if (jc == 0) {
            g_c[parity ^ 1][b * HDIM + j] = c;
            g_h[b * HDIM + j] = h;
        }
        hs[j] = h;
    }
    __syncthreads();

    // GEMV: 1 thread per output (tid), 512 k, 8 accumulators
    const float* W = ((jc == 0) ? Wproj : Watt) + tid;
    float a[8];
    #pragma unroll
    for (int i = 0; i < 8; i++) a[i] = 0.f;
    #pragma unroll 4
    for (int k = 0; k < 512; k += 8) {
        #pragma unroll
        for (int i = 0; i < 8; i++)
            a[i] += hs[k + i] * W[(size_t)(k + i) * 256];
    }
    float s = ((a[0] + a[1]) + (a[2] + a[3])) + ((a[4] + a[5]) + (a[6] + a[7]));

    if (jc == 0) {
        __nv_bfloat16 hi = __float2bfloat16(s);
        __nv_bfloat16 lo = __float2bfloat16(s - __bfloat162float(hi));
        g_hpb[b * EMB + tid] = hi;
        g_hpb[(64 + b) * EMB + tid] = lo;
        __threadfence();
        __syncthreads();
        if (tid == 0) { atomicAdd(&g_flag_hp, 1u); atomicAdd(&g_flag_all, 1u); }
        return;
    }

    // jc == 1: hW in smem -> attention(t+1) -> g_ctx
    red[tid] = s;
    vs[tid] = vatt[tid];
    __syncthreads();
    int warp = tid >> 5, lane = tid & 31;
    for (int n = warp; n < N; n += 8) {
        const float* uv = g_Uv + (size_t)(b * N + n) * ATTD;
        float p = 0.f;
        #pragma unroll
        for (int q = 0; q < 8; q++) {
            int aidx = lane + 32 * q;
            p += tanh_fast(red[aidx] + uv[aidx]) * vs[aidx];
        }
        #pragma unroll
        for (int off = 16; off > 0; off >>= 1)
            p += __shfl_down_sync(0xffffffffu, p, off);
        if (lane == 0) es[n] = p;
    }
    __syncthreads();
    float v = (tid < N) ? es[tid] : -INFINITY;
    red[tid] = v;                     // red reused for reductions
    __syncthreads();
    for (int st = 128; st > 0; st >>= 1) {
        if (tid < st) red[tid] = fmaxf(red[tid], red[tid + st]);
        __syncthreads();
    }
    float mx = red[0];
    __syncthreads();
    float ex = (tid < N) ? expf(v - mx) : 0.f;
    red[tid] = ex;
    __syncthreads();
    for (int st = 128; st > 0; st >>= 1) {
        if (tid < st) red[tid] += red[tid + st];
        __syncthreads();
    }
    float inv = 1.f / red[0];
    __syncthreads();
    if (tid < N) es[tid] = ex * inv;
    __syncthreads();
    // ctx: full 196-dot per thread, 8 accumulators (MLP)
    const float* vp = V + (size_t)b * N * VDIM + tid;
    float ca[8];
    #pragma unroll
    for (int i = 0; i < 8; i++) ca[i] = 0.f;
    int n = 0;
    #pragma unroll 3
    for (; n + 8 <= N; n += 8) {
        #pragma unroll
        for (int i = 0; i < 8; i++)
            ca[i] += es[n + i] * vp[(size_t)(n + i) * VDIM];
    }
    for (; n < N; n++) ca[0] += es[n] * vp[(size_t)n * VDIM];
    g_ctx[b * VDIM + tid] =
        ((ca[0] + ca[1]) + (ca[2] + ca[3])) + ((ca[4] + ca[5]) + (ca[6] + ca[7]));
    __threadfence();
    __syncthreads();
    if (tid == 0) atomicAdd(&g_flag_all, 1u);
}

// ================= logits body (mma.sync bf16 hi/lo), 256 threads =================
#define SA  0
#define SBH 32768
#define SBL (SBH + 34816)
#define SM_LOG (SBL + 34816)   // 102400

__device__ __forceinline__ void logits_body(char* smc, float* __restrict__ out,
                                            int t, int v0, unsigned hp_target) {
    const unsigned sb = smem_u32(smc);
    int tid = threadIdx.x;
    int wid = tid >> 5, lane = tid & 31;
    int wr = wid & 3, wc = wid >> 2;
    bool hiwarp = (wr < 2);

    float d[16][4];
    #pragma unroll
    for (int f = 0; f < 16; f++) { d[f][0] = d[f][1] = d[f][2] = d[f][3] = 0.f; }

    int bmat = lane >> 3, brow = lane & 7;
    int bn_local = ((bmat >> 1) << 3) + brow;
    unsigned bkoff = (unsigned)((bmat & 1) << 3) * 2;

    #pragma unroll
    for (int kc = 0; kc < 2; kc++) {
        // B tiles first (independent of producers)
        for (int i = tid; i < 2048; i += 256) {
            int n = i >> 4, u = i & 15;
            size_t go = (size_t)(v0 + n) * 512 + kc * 256 + u * 16;
            *(uint4*)(smc + SBH + n * 272 + u * 16) = *(const uint4*)((const char*)g_eh + go);
            *(uint4*)(smc + SBL + n * 272 + u * 16) = *(const uint4*)((const char*)g_el + go);
        }
        if (kc == 0 && hp_target) wait_flag(&g_flag_hp, hp_target);
        // A tile (depends on g_hpb)
        for (int i = tid; i < 2048; i += 256) {
            int m = i >> 4, u = i & 15;
            *(uint4*)(smc + SA + m * 256 + ((u ^ (m & 7)) << 4)) =
                *(const uint4*)((const char*)g_hpb + (size_t)m * 512 + kc * 256 + u * 16);
        }
        __syncthreads();

        #pragma unroll
        for (int ks = 0; ks < 8; ks++) {
            unsigned a[2][4];
            #pragma unroll
            for (int mi = 0; mi < 2; mi++) {
                int m = wr * 32 + mi * 16 + ((lane >> 3) & 1) * 8 + (lane & 7);
                int u = ks * 2 + (lane >> 4);
                unsigned addr = sb + SA + m * 256 + ((u ^ (m & 7)) << 4);
                asm volatile(
                    "ldmatrix.sync.aligned.m8n8.x4.shared.b16 {%0,%1,%2,%3}, [%4];"
                    : "=r"(a[mi][0]), "=r"(a[mi][1]), "=r"(a[mi][2]), "=r"(a[mi][3])
                    : "r"(addr));
            }
            unsigned bko = (unsigned)(ks * 32) + bkoff;
            #pragma unroll
            for (int np = 0; np < 4; np++) {
                unsigned brow_addr = sb + SBH +
                    (unsigned)((wc * 64 + np * 16 + bn_local) * 272) + bko;
                unsigned bh[4];
                asm volatile(
                    "ldmatrix.sync.aligned.m8n8.x4.shared.b16 {%0,%1,%2,%3}, [%4];"
                    : "=r"(bh[0]), "=r"(bh[1]), "=r"(bh[2]), "=r"(bh[3])
                    : "r"(brow_addr));
                #pragma unroll
                for (int half = 0; half < 2; half++) {
                    int f0 = np * 2 + half;
                    #pragma unroll
                    for (int mi = 0; mi < 2; mi++) {
                        int f = mi * 8 + f0;
                        asm volatile(
                            "mma.sync.aligned.m16n8k16.row.col.f32.bf16.bf16.f32 "
                            "{%0,%1,%2,%3}, {%4,%5,%6,%7}, {%8,%9}, {%0,%1,%2,%3};"
                            : "+f"(d[f][0]), "+f"(d[f][1]), "+f"(d[f][2]), "+f"(d[f][3])
                            : "r"(a[mi][0]), "r"(a[mi][1]), "r"(a[mi][2]), "r"(a[mi][3]),
                              "r"(bh[half * 2]), "r"(bh[half * 2 + 1]));
                    }
                }
                if (hiwarp) {
                    unsigned blo_addr = brow_addr + (SBL - SBH);
                    unsigned bl[4];
                    asm volatile(
                        "ldmatrix.sync.aligned.m8n8.x4.shared.b16 {%0,%1,%2,%3}, [%4];"
                        : "=r"(bl[0]), "=r"(bl[1]), "=r"(bl[2]), "=r"(bl[3])
                        : "r"(blo_addr));
                    #pragma unroll
                    for (int half = 0; half < 2; half++) {
                        int f0 = np * 2 + half;
                        #pragma unroll
                        for (int mi = 0; mi < 2; mi++) {
                            int f = mi * 8 + f0;
                            asm volatile(
                                "mma.sync.aligned.m16n8k16.row.col.f32.bf16.bf16.f32 "
                                "{%0,%1,%2,%3}, {%4,%5,%6,%7}, {%8,%9}, {%0,%1,%2,%3};"
                                : "+f"(d[f][0]), "+f"(d[f][1]), "+f"(d[f][2]), "+f"(d[f][3])
                                : "r"(a[mi][0]), "r"(a[mi][1]), "r"(a[mi][2]), "r"(a[mi][3]),
                                  "r"(bl[half * 2]), "r"(bl[half * 2 + 1]));
                        }
                    }
                }
            }
        }
        __syncthreads();
    }

    float* epi = (float*)(smc + SA);
    if (wr >= 2) {
        #pragma unroll
        for (int mi = 0; mi < 2; mi++) {
            int r0 = (wr - 2) * 32 + mi * 16 + (lane >> 2);
            #pragma unroll
            for (int nf = 0; nf < 8; nf++) {
                int f = mi * 8 + nf;
                int col = wc * 64 + nf * 8 + (lane & 3) * 2;
                epi[r0 * 128 + col]           = d[f][0];
                epi[r0 * 128 + col + 1]       = d[f][1];
                epi[(r0 + 8) * 128 + col]     = d[f][2];
                epi[(r0 + 8) * 128 + col + 1] = d[f][3];
            }
        }
    }
    __syncthreads();
    if (wr < 2) {
        #pragma unroll
        for (int mi = 0; mi < 2; mi++) {
            int b0 = wr * 32 + mi * 16 + (lane >> 2);
            #pragma unroll
            for (int nf = 0; nf < 8; nf++) {
                int f = mi * 8 + nf;
                int col = wc * 64 + nf * 8 + (lane & 3) * 2;
                float2 r0v = make_float2(d[f][0] + epi[b0 * 128 + col],
                                         d[f][1] + epi[b0 * 128 + col + 1]);
                float2 r1v = make_float2(d[f][2] + epi[(b0 + 8) * 128 + col],
                                         d[f][3] + epi[(b0 + 8) * 128 + col + 1]);
                *(float2*)(out + ((size_t)b0 * STEPS + t) * VOCAB + v0 + col) = r0v;
                *(float2*)(out + ((size_t)(b0 + 8) * STEPS + t) * VOCAB + v0 + col) = r1v;
            }
        }
    }
}

// ================= mega step kernel: producers + logits(t) + gates(t+1) =================
// grid = 634 blocks x 256 threads, dyn smem = SM_LOG
__global__ void __launch_bounds__(256, 2)
k_step(float* __restrict__ out, int t,
       const float* __restrict__ embed, const int* __restrict__ y,
       const float* __restrict__ Wih, const float* __restrict__ Whh,
       const float* __restrict__ bih, const float* __restrict__ bhh,
       const float* __restrict__ Wproj, const float* __restrict__ Watt,
       const float* __restrict__ vatt, const float* __restrict__ V, int parity) {
    extern __shared__ char smc[];
    int bid = blockIdx.x;
    if (bid < 128) {
        producer_body(smc, bih, bhh, Wproj, Watt, vatt, V, parity, bid >> 1, bid & 1);
    } else if (bid < 378) {
        logits_body(smc, out, t, (bid - 128) * 128, 64u * (unsigned)(t + 1));
    } else {
        int idx = bid - 378;
        // gates for step t+1 (t+1 == STEPS computed harmlessly; never consumed)
        gates_body(smc, embed, y, Wih, Whh, t + 1, (idx & 31) * 64, idx >> 5,
                   128u * (unsigned)(t + 1));
    }
}

// ---------------- launch ----------------
extern "C" void kernel_launch(void* const* d_in, const int* in_sizes, int n_in,
                              void* d_out, int out_size) {
    const float* V      = (const float*)d_in[0];
    const int*   y      = (const int*)  d_in[1];
    const float* embed  = (const float*)d_in[2];
    const float* W_att  = (const float*)d_in[3];
    const float* U_att  = (const float*)d_in[4];
    const float* v_att  = (const float*)d_in[5];
    const float* W_ih   = (const float*)d_in[6];
    const float* W_hh   = (const float*)d_in[7];
    const float* b_ih   = (const float*)d_in[8];
    const float* b_hh   = (const float*)d_in[9];
    const float* W_inith = (const float*)d_in[10];
    const float* b_inith = (const float*)d_in[11];
    const float* W_initc = (const float*)d_in[12];
    const float* b_initc = (const float*)d_in[13];
    const float* W_proj  = (const float*)d_in[14];
    float* out = (float*)d_out;

    const int SMEM_GATES = (128 * 68 + 128 * 64) * sizeof(float);  // 67584
    cudaFuncSetAttribute(k_gates, cudaFuncAttributeMaxDynamicSharedMemorySize, SMEM_GATES);
    cudaFuncSetAttribute(k_step,  cudaFuncAttributeMaxDynamicSharedMemorySize, SM_LOG);

    k_reset<<<1, 1>>>();
    k_init_hc<<<B, 512>>>(V, W_inith, b_inith, W_initc, b_initc);
    k_uv<<<(B * N) / UV_ROWS, 256>>>(V, U_att);
    k_esplit<<<(VOCAB * EMB) / 512, 256>>>(embed);
    k_hw0<<<B, 1024>>>(W_att);                                   // hW(h0)
    k_att0<<<B, 512>>>(v_att, V);                                // ctx(0)
    k_gates<<<256, 256, SMEM_GATES>>>(embed, y, W_ih, W_hh, 0);  // gates(0)

    for (int t = 0; t < STEPS; t++) {
        k_step<<<634, 256, SM_LOG>>>(out, t, embed, y, W_ih, W_hh,
                                     b_ih, b_hh, W_proj, W_att, v_att, V, t & 1);
    }
}